// round 3
// baseline (speedup 1.0000x reference)
#include <cuda_runtime.h>
#include <math.h>
#include <float.h>

#define N_      2048
#define DIM_    1024
#define H_      16
#define KVH_    8
#define GQ_     2
#define D_      64
#define WS_     64
#define CBS_    32
#define STRIDE_ 16
#define SEL_BLK_ 32
#define NSEL_   4
#define NMEM_   1
#define NCB_    128
#define NFB_    64
#define HID_    2048
#define SCALE_  0.125f
#define QKVW_   2048            /* (H + 2*KVH) * D */
#define CJ_     (NMEM_ + NCB_)  /* 129 */
#define CJP_    144             /* CJ padded to mult of 16 */

typedef unsigned long long ull;

// ---------------- scratch (static device allocations) -----------------------
__device__ float g_x[N_ * DIM_];
__device__ float g_qkv[N_ * QKVW_];
__device__ float g_kwflat[KVH_ * NCB_ * HID_];
__device__ float g_vwflat[KVH_ * NCB_ * HID_];
__device__ float g_h1[KVH_ * NCB_ * HID_];
__device__ float g_ckraw[KVH_ * NCB_ * D_];
__device__ float g_cvraw[KVH_ * NCB_ * D_];
__device__ float g_ckT[KVH_ * D_ * CJP_];     // [kh][d][jp]
__device__ float g_cvpad[KVH_ * CJP_ * D_];   // [kh][jp][d], pad rows zero
__device__ float g_qc[H_ * N_ * D_];          // non-rope q, [h][n][d]
__device__ float g_csim[KVH_ * (GQ_ * N_) * CJP_];
__device__ float g_rq[H_ * N_ * D_];
__device__ float g_rk[KVH_ * N_ * D_];
__device__ float g_cout[H_ * N_ * D_];
__device__ float g_fout[H_ * N_ * D_];
__device__ float g_sout[H_ * N_ * D_];
__device__ float g_imp[KVH_ * N_ * NFB_];
__device__ int   g_selidx[KVH_ * N_ * 5];
__device__ int   g_selflag[KVH_ * N_ * 4];
__device__ float g_gates[N_ * H_ * 3];
__device__ float g_comb[N_ * DIM_];
__device__ float g_part[4 * N_ * 64];         // split-K partials (max use)

// ---------------- RMSNorm ---------------------------------------------------
__global__ void rmsnorm_kernel(const float* __restrict__ inp,
                               const float* __restrict__ gamma) {
    int row = blockIdx.x;
    const float* r = inp + (size_t)row * DIM_;
    float s = 0.f;
    for (int j = threadIdx.x; j < DIM_; j += blockDim.x) { float v = r[j]; s += v * v; }
    __shared__ float sh[32];
    for (int o = 16; o; o >>= 1) s += __shfl_down_sync(0xffffffffu, s, o);
    if ((threadIdx.x & 31) == 0) sh[threadIdx.x >> 5] = s;
    __syncthreads();
    if (threadIdx.x < 32) {
        s = (threadIdx.x < (blockDim.x >> 5)) ? sh[threadIdx.x] : 0.f;
        for (int o = 16; o; o >>= 1) s += __shfl_down_sync(0xffffffffu, s, o);
        if (threadIdx.x == 0) sh[0] = rsqrtf(s / (float)DIM_ + 1.1920929e-07f);
    }
    __syncthreads();
    float rs = sh[0];
    for (int j = threadIdx.x; j < DIM_; j += blockDim.x)
        g_x[(size_t)row * DIM_ + j] = r[j] * rs * gamma[j];
}

// ---------------- packed-fp32 helpers ---------------------------------------
__device__ __forceinline__ ull pack2_dup(float x) {
    ull r;
    asm("mov.b64 %0, {%1, %1};" : "=l"(r) : "f"(x));
    return r;
}
__device__ __forceinline__ void fma2(ull& acc, ull a, ull b) {
    asm("fma.rn.f32x2 %0, %1, %2, %0;" : "+l"(acc) : "l"(a), "l"(b));
}
__device__ __forceinline__ float lo32(ull v) { return __uint_as_float((unsigned)v); }
__device__ __forceinline__ float hi32(ull v) { return __uint_as_float((unsigned)(v >> 32)); }

// ---------------- SGEMM2: 64x128 tile, FFMA2 inner loop ----------------------
// A (M,K) lda, B (K,N) ldb row-major. 256 thr, per-thread 4 rows x 8 cols.
// Requires M % 64 == 0, N % 128 == 0, K % 16 == 0.
template <int ACT, bool BIAS>
__global__ void sgemm2_kernel(const float* __restrict__ A, int lda,
                              const float* __restrict__ B, int ldb,
                              const float* __restrict__ bias,
                              float* __restrict__ C, int ldc,
                              int M, int Ncols, int K) {
    __shared__ float As[16][68];
    __shared__ float Bs[16][128];
    const int bm = blockIdx.y * 64, bn = blockIdx.x * 128;
    const int tid = threadIdx.x;
    const int tx = tid & 15, ty = tid >> 4;        // tx: 8-col group, ty: 4-row group
    const int arow = tid >> 2, acol4 = (tid & 3) << 2;
    const int brow = tid >> 4, bcol8 = (tid & 15) << 3;
    ull acc[4][4];
#pragma unroll
    for (int i = 0; i < 4; i++)
#pragma unroll
        for (int j = 0; j < 4; j++) acc[i][j] = 0ull;

    for (int k0 = 0; k0 < K; k0 += 16) {
        float4 av = *(const float4*)(A + (size_t)(bm + arow) * lda + k0 + acol4);
        As[acol4 + 0][arow] = av.x; As[acol4 + 1][arow] = av.y;
        As[acol4 + 2][arow] = av.z; As[acol4 + 3][arow] = av.w;
        float4 b0 = *(const float4*)(B + (size_t)(k0 + brow) * ldb + bn + bcol8);
        float4 b1 = *(const float4*)(B + (size_t)(k0 + brow) * ldb + bn + bcol8 + 4);
        *(float4*)&Bs[brow][bcol8] = b0;
        *(float4*)&Bs[brow][bcol8 + 4] = b1;
        __syncthreads();
#pragma unroll
        for (int k = 0; k < 16; k++) {
            float4 a4 = *(const float4*)&As[k][ty * 4];
            ull a2[4];
            a2[0] = pack2_dup(a4.x); a2[1] = pack2_dup(a4.y);
            a2[2] = pack2_dup(a4.z); a2[3] = pack2_dup(a4.w);
            const ull* b64 = (const ull*)&Bs[k][tx * 8];
            ull bb0 = b64[0], bb1 = b64[1], bb2 = b64[2], bb3 = b64[3];
#pragma unroll
            for (int i = 0; i < 4; i++) {
                fma2(acc[i][0], a2[i], bb0);
                fma2(acc[i][1], a2[i], bb1);
                fma2(acc[i][2], a2[i], bb2);
                fma2(acc[i][3], a2[i], bb3);
            }
        }
        __syncthreads();
    }
#pragma unroll
    for (int i = 0; i < 4; i++) {
        int r = bm + ty * 4 + i;
        float* crow = C + (size_t)r * ldc + bn + tx * 8;
#pragma unroll
        for (int j = 0; j < 4; j++) {
            float vl = lo32(acc[i][j]), vh = hi32(acc[i][j]);
            if (BIAS) {
                vl += bias[bn + tx * 8 + 2 * j];
                vh += bias[bn + tx * 8 + 2 * j + 1];
            }
            if (ACT == 1) { vl = fmaxf(vl, 0.f); vh = fmaxf(vh, 0.f); }
            crow[2 * j] = vl;
            crow[2 * j + 1] = vh;
        }
    }
}

// ---------------- SGEMM (generalized, 64x64; for narrow/odd shapes) ---------
template <int ACT, bool BIAS>
__global__ void sgemm_kernel(const float* __restrict__ A, int lda, long sA,
                             const float* __restrict__ B, int ldb, long sB,
                             const float* __restrict__ bias,
                             float* __restrict__ C, int ldc, long sC,
                             int M, int Ncols, int K) {
    __shared__ float As[16][68];
    __shared__ float Bs[16][64];
    A += (size_t)blockIdx.z * sA;
    B += (size_t)blockIdx.z * sB;
    C += (size_t)blockIdx.z * sC;
    const int bm = blockIdx.y * 64, bn = blockIdx.x * 64;
    const int tid = threadIdx.x;
    const int tx = tid & 15, ty = tid >> 4;
    const int arow = tid >> 2, acol4 = (tid & 3) << 2;
    const int brow = tid >> 4, bcol4 = (tid & 15) << 2;
    float acc[4][4] = {};
    for (int k0 = 0; k0 < K; k0 += 16) {
        float4 av = make_float4(0.f, 0.f, 0.f, 0.f);
        if (bm + arow < M)
            av = *(const float4*)(A + (size_t)(bm + arow) * lda + k0 + acol4);
        As[acol4 + 0][arow] = av.x; As[acol4 + 1][arow] = av.y;
        As[acol4 + 2][arow] = av.z; As[acol4 + 3][arow] = av.w;
        float4 bv = make_float4(0.f, 0.f, 0.f, 0.f);
        if (bn + bcol4 < Ncols)
            bv = *(const float4*)(B + (size_t)(k0 + brow) * ldb + bn + bcol4);
        *(float4*)&Bs[brow][bcol4] = bv;
        __syncthreads();
#pragma unroll
        for (int k = 0; k < 16; k++) {
            float a[4], b[4];
#pragma unroll
            for (int i = 0; i < 4; i++) a[i] = As[k][ty * 4 + i];
#pragma unroll
            for (int j = 0; j < 4; j++) b[j] = Bs[k][tx * 4 + j];
#pragma unroll
            for (int i = 0; i < 4; i++)
#pragma unroll
                for (int j = 0; j < 4; j++) acc[i][j] += a[i] * b[j];
        }
        __syncthreads();
    }
#pragma unroll
    for (int i = 0; i < 4; i++) {
        int r = bm + ty * 4 + i;
        if (r >= M) continue;
#pragma unroll
        for (int j = 0; j < 4; j++) {
            int c = bn + tx * 4 + j;
            if (c >= Ncols) continue;
            float v = acc[i][j];
            if (BIAS) v += bias[c];
            if (ACT == 1) v = fmaxf(v, 0.f);
            C[(size_t)r * ldc + c] = v;
        }
    }
}

// ---------------- split-K reduce (Z=4) ---------------------------------------
template <int ACT>
__global__ void reduce4_kernel(const float* __restrict__ part,
                               const float* __restrict__ bias,
                               float* __restrict__ out, int total, int ncols) {
    int idx = blockIdx.x * blockDim.x + threadIdx.x;
    if (idx >= total) return;
    float v = part[idx] + part[idx + total] + part[idx + 2 * total] +
              part[idx + 3 * total] + bias[idx % ncols];
    if (ACT == 2) v = 1.f / (1.f + expf(-v));
    out[idx] = v;
}

// ---------------- build compression windows ---------------------------------
__global__ void build_windows_kernel(const float* __restrict__ k_pos,
                                     const float* __restrict__ v_pos) {
    int idx = blockIdx.x * blockDim.x + threadIdx.x;
    if (idx >= KVH_ * NCB_ * CBS_ * D_) return;
    int d  = idx % D_;
    int t  = (idx / D_) % CBS_;
    int c  = (idx / (D_ * CBS_)) % NCB_;
    int kh = idx / (D_ * CBS_ * NCB_);
    int pos = c * STRIDE_ + t - (CBS_ - STRIDE_);
    float kv = 0.f, vv = 0.f;
    if (pos >= 0) {
        kv = g_qkv[(size_t)pos * QKVW_ + H_ * D_ + kh * D_ + d];
        vv = g_qkv[(size_t)pos * QKVW_ + (H_ + KVH_) * D_ + kh * D_ + d];
    }
    kv += k_pos[(kh * CBS_ + t) * D_ + d];
    vv += v_pos[(kh * CBS_ + t) * D_ + d];
    size_t row = (size_t)kh * NCB_ + c;
    g_kwflat[row * HID_ + t * D_ + d] = kv;
    g_vwflat[row * HID_ + t * D_ + d] = vv;
}

// ---------------- assemble ckT / cvpad ---------------------------------------
__global__ void assemble_c_kernel(const float* __restrict__ mem_kv) {
    int idx = blockIdx.x * blockDim.x + threadIdx.x;
    if (idx >= KVH_ * CJP_ * D_) return;
    int d  = idx % D_;
    int j  = (idx / D_) % CJP_;
    int kh = idx / (D_ * CJP_);
    float kvv = 0.f, vvv = 0.f;
    if (j < NMEM_) {
        kvv = mem_kv[((0 * KVH_ + kh) * NMEM_ + j) * D_ + d];
        vvv = mem_kv[((1 * KVH_ + kh) * NMEM_ + j) * D_ + d];
    } else if (j < CJ_) {
        kvv = g_ckraw[((size_t)kh * NCB_ + (j - NMEM_)) * D_ + d];
        vvv = g_cvraw[((size_t)kh * NCB_ + (j - NMEM_)) * D_ + d];
    }
    g_ckT[((size_t)kh * D_ + d) * CJP_ + j] = kvv;
    g_cvpad[((size_t)kh * CJP_ + j) * D_ + d] = vvv;
}

// ---------------- RoPE (+ extract non-rope q) --------------------------------
__global__ void rope_kernel() {
    int idx = blockIdx.x * blockDim.x + threadIdx.x;
    if (idx >= (H_ + KVH_) * N_ * (D_ / 2)) return;
    int m = idx % (D_ / 2);
    int n = (idx / (D_ / 2)) % N_;
    int h = idx / ((D_ / 2) * N_);
    // 1/theta^(2m/D) = exp2(-(2m/D)*log2(theta))
    float inv = exp2f(-(float)m * (2.0f / (float)D_) * 13.2877123795f);
    float ang = (float)n * inv;
    float c = cosf(ang), s = sinf(ang);
    const float* src;
    float* dst;
    if (h < H_) {
        src = g_qkv + (size_t)n * QKVW_ + h * D_;
        dst = g_rq + ((size_t)h * N_ + n) * D_;
    } else {
        int kh = h - H_;
        src = g_qkv + (size_t)n * QKVW_ + H_ * D_ + kh * D_;
        dst = g_rk + ((size_t)kh * N_ + n) * D_;
    }
    float a = src[2 * m], b = src[2 * m + 1];
    dst[2 * m]     = a * c - b * s;
    dst[2 * m + 1] = b * c + a * s;
    if (h < H_) {
        float* qd = g_qc + ((size_t)h * N_ + n) * D_;
        qd[2 * m] = a; qd[2 * m + 1] = b;
    }
}

// ---------------- importance (pre-softmax csim) ------------------------------
__global__ void importance_kernel() {
    int idx = blockIdx.x * blockDim.x + threadIdx.x;  // KVH*N*NFB
    if (idx >= KVH_ * N_ * NFB_) return;
    int fb = idx % NFB_;
    int i  = (idx / NFB_) % N_;
    int kh = idx / (NFB_ * N_);
    const float* base = g_csim + (size_t)kh * (GQ_ * N_) * CJP_;
    int c = NMEM_ + 2 * fb;
    float v = base[(size_t)i * CJP_ + c] + base[(size_t)i * CJP_ + c + 1] +
              base[(size_t)(N_ + i) * CJP_ + c] + base[(size_t)(N_ + i) * CJP_ + c + 1];
    g_imp[((size_t)kh * N_ + i) * NFB_ + fb] = 0.25f * SCALE_ * v;
}

// ---------------- compressed softmax (in-place, warp per row) ----------------
__global__ void csoftmax_kernel() {
    int row  = blockIdx.x * 8 + (threadIdx.x >> 5);  // 0..KVH*GQ*N-1
    int lane = threadIdx.x & 31;
    float* p = g_csim + (size_t)row * CJP_;
    float v0 = p[lane] * SCALE_, v1 = p[lane + 32] * SCALE_;
    float v2 = p[lane + 64] * SCALE_, v3 = p[lane + 96] * SCALE_;
    float v4 = (lane == 0) ? p[128] * SCALE_ : -FLT_MAX;
    float m = fmaxf(fmaxf(fmaxf(v0, v1), fmaxf(v2, v3)), v4);
    for (int o = 16; o; o >>= 1) m = fmaxf(m, __shfl_xor_sync(0xffffffffu, m, o));
    float e0 = expf(v0 - m), e1 = expf(v1 - m), e2 = expf(v2 - m), e3 = expf(v3 - m);
    float e4 = (lane == 0) ? expf(v4 - m) : 0.f;
    float s = e0 + e1 + e2 + e3 + e4;
    for (int o = 16; o; o >>= 1) s += __shfl_xor_sync(0xffffffffu, s, o);
    float inv = 1.f / s;
    p[lane] = e0 * inv; p[lane + 32] = e1 * inv;
    p[lane + 64] = e2 * inv; p[lane + 96] = e3 * inv;
    if (lane == 0) p[128] = e4 * inv;
    if (lane >= 1 && lane < 16) p[128 + lane] = 0.f;  // zero pad cols
}

// ---------------- top-k (warp per row) ----------------------------------------
__global__ void topk_kernel() {
    int row  = blockIdx.x * 8 + (threadIdx.x >> 5);  // KVH*N rows
    int lane = threadIdx.x & 31;
    int i = row & (N_ - 1);
    int qb = i >> 5;
    const float* ip = g_imp + (size_t)row * NFB_;
    float v0 = (lane == qb)      ? -FLT_MAX : ip[lane];
    float v1 = (lane + 32 == qb) ? -FLT_MAX : ip[lane + 32];
    float m = fmaxf(fmaxf(v0, v1), -1000.f);
    for (int o = 16; o; o >>= 1) m = fmaxf(m, __shfl_xor_sync(0xffffffffu, m, o));
    float s = expf(v0 - m) + expf(v1 - m);
    for (int o = 16; o; o >>= 1) s += __shfl_xor_sync(0xffffffffu, s, o);
    s += expf(-1000.f - m);
    float inv = 1.f / s;
    float p0 = expf(v0 - m) * inv, p1 = expf(v1 - m) * inv;
#pragma unroll
    for (int sel = 0; sel < NSEL_; sel++) {
        float bv; int bi;
        if (p0 >= p1) { bv = p0; bi = lane; } else { bv = p1; bi = lane + 32; }
        for (int o = 16; o; o >>= 1) {
            float ov = __shfl_xor_sync(0xffffffffu, bv, o);
            int   oi = __shfl_xor_sync(0xffffffffu, bi, o);
            if (ov > bv || (ov == bv && oi < bi)) { bv = ov; bi = oi; }
        }
        if (lane == 0) {
            g_selidx[(size_t)row * 5 + sel] = bi;
            g_selflag[(size_t)row * 4 + sel] = (bv > 1e-10f) ? 1 : 0;
        }
        if (bi == lane) p0 = -1.f;
        if (bi == lane + 32) p1 = -1.f;
    }
    if (lane == 0) g_selidx[(size_t)row * 5 + 4] = qb;
}

// ---------------- fine attention (warp-per-keygroup QK) ----------------------
__global__ void fattn_kernel() {
    int i  = blockIdx.x & (N_ - 1);
    int kh = blockIdx.x >> 11;
    __shared__ float qs[2][D_];
    __shared__ float sims[2][5 * SEL_BLK_];
    __shared__ int   sblk[5];
    __shared__ int   sfl[5];
    __shared__ float red[2][2];
    int tid = threadIdx.x;  // 160 = 5 warps
    int w = tid >> 5, lane = tid & 31;
    if (tid < 5) {
        sblk[tid] = g_selidx[((size_t)kh * N_ + i) * 5 + tid];
        sfl[tid]  = (tid < 4) ? g_selflag[((size_t)kh * N_ + i) * 4 + tid] : 1;
    }
    if (tid < 128) {
        int g = tid >> 6, d = tid & 63;
        qs[g][d] = g_rq[(((size_t)(kh * GQ_ + g)) * N_ + i) * D_ + d];
    }
    __syncthreads();
    {
        float q0a = qs[0][lane], q0b = qs[0][lane + 32];
        float q1a = qs[1][lane], q1b = qs[1][lane + 32];
        int blk = sblk[w];
        bool grpvalid = (w < 4) ? (sfl[w] != 0) : true;
        int lim = (w == 4) ? (i & 31) : 31;
        const float* kbase = g_rk + ((size_t)kh * N_ + blk * SEL_BLK_) * D_;
        for (int kk = 0; kk < SEL_BLK_; kk++) {
            float s0 = -FLT_MAX / 10.f, s1 = -FLT_MAX / 10.f;
            if (grpvalid && kk <= lim) {
                float ka = kbase[kk * D_ + lane], kb = kbase[kk * D_ + lane + 32];
                float p0 = q0a * ka + q0b * kb;
                float p1 = q1a * ka + q1b * kb;
                for (int o = 16; o; o >>= 1) {
                    p0 += __shfl_xor_sync(0xffffffffu, p0, o);
                    p1 += __shfl_xor_sync(0xffffffffu, p1, o);
                }
                s0 = p0 * SCALE_; s1 = p1 * SCALE_;
            }
            if (lane == 0) { sims[0][w * 32 + kk] = s0; sims[1][w * 32 + kk] = s1; }
        }
    }
    __syncthreads();
    if (tid < 64) {
        int g = tid >> 5, l = tid & 31;
        float m = -FLT_MAX;
        for (int j = l; j < 160; j += 32) m = fmaxf(m, sims[g][j]);
        for (int o = 16; o; o >>= 1) m = fmaxf(m, __shfl_xor_sync(0xffffffffu, m, o));
        float sm = 0.f;
        for (int j = l; j < 160; j += 32) sm += expf(sims[g][j] - m);
        for (int o = 16; o; o >>= 1) sm += __shfl_xor_sync(0xffffffffu, sm, o);
        if (l == 0) { red[g][0] = m; red[g][1] = sm; }
    }
    __syncthreads();
    for (int j = tid; j < 320; j += 160) {
        int g = j / 160, jj = j % 160;
        sims[g][jj] = expf(sims[g][jj] - red[g][0]) / red[g][1];
    }
    __syncthreads();
    if (tid < 128) {
        int g = tid >> 6, d = tid & 63;
        const float* vbase = g_qkv + (size_t)(H_ + KVH_) * D_ + kh * D_ + d;
        float acc = 0.f;
#pragma unroll
        for (int s = 0; s < 5; s++) {
            int pb = sblk[s] * SEL_BLK_;
#pragma unroll 8
            for (int t = 0; t < SEL_BLK_; t++)
                acc += sims[g][s * 32 + t] * vbase[(size_t)(pb + t) * QKVW_];
        }
        g_fout[(((size_t)(kh * GQ_ + g)) * N_ + i) * D_ + d] = acc;
    }
}

// ---------------- sliding-window attention (tiled, smem) ---------------------
__global__ void sattn_kernel() {
    extern __shared__ float sm[];
    float* Ks = sm;                        // 128 x 65
    float* Qs = sm + 128 * 65;             // 64 x 65
    float* Ps = Qs + 64 * 65;              // 64 x 128
    int tIdx = blockIdx.x, h = blockIdx.y, kh = h >> 1;
    int i0 = tIdx * 64;
    int tid = threadIdx.x, w = tid >> 5, lane = tid & 31;
    for (int idx = tid; idx < 64 * 64; idx += 256) {
        int r = idx >> 6, d = idx & 63;
        Qs[r * 65 + d] = g_rq[((size_t)h * N_ + i0 + r) * D_ + d];
    }
    for (int idx = tid; idx < 128 * 64; idx += 256) {
        int j = idx >> 6, d = idx & 63;
        int p = i0 - 64 + j;
        Ks[j * 65 + d] = (p >= 0) ? g_rk[((size_t)kh * N_ + p) * D_ + d] : 0.f;
    }
    __syncthreads();
#pragma unroll
    for (int rr = 0; rr < 8; rr++) {
        int r = w * 8 + rr;
        int j0 = lane, j1 = lane + 32, j2 = lane + 64, j3 = lane + 96;
        float a0 = 0.f, a1 = 0.f, a2 = 0.f, a3 = 0.f;
        for (int d = 0; d < 64; d++) {
            float q = Qs[r * 65 + d];
            a0 += q * Ks[j0 * 65 + d]; a1 += q * Ks[j1 * 65 + d];
            a2 += q * Ks[j2 * 65 + d]; a3 += q * Ks[j3 * 65 + d];
        }
        float s0, s1, s2, s3;
        {
            bool ok;
            ok = (j0 >= r + 1) && (j0 <= r + 64) && (i0 - 64 + j0 >= 0);
            s0 = ok ? a0 * SCALE_ : -FLT_MAX;
            ok = (j1 >= r + 1) && (j1 <= r + 64) && (i0 - 64 + j1 >= 0);
            s1 = ok ? a1 * SCALE_ : -FLT_MAX;
            ok = (j2 >= r + 1) && (j2 <= r + 64) && (i0 - 64 + j2 >= 0);
            s2 = ok ? a2 * SCALE_ : -FLT_MAX;
            ok = (j3 >= r + 1) && (j3 <= r + 64) && (i0 - 64 + j3 >= 0);
            s3 = ok ? a3 * SCALE_ : -FLT_MAX;
        }
        float m = fmaxf(fmaxf(s0, s1), fmaxf(s2, s3));
        for (int o = 16; o; o >>= 1) m = fmaxf(m, __shfl_xor_sync(0xffffffffu, m, o));
        float e0 = expf(s0 - m), e1 = expf(s1 - m), e2 = expf(s2 - m), e3 = expf(s3 - m);
        float su = e0 + e1 + e2 + e3;
        for (int o = 16; o; o >>= 1) su += __shfl_xor_sync(0xffffffffu, su, o);
        float inv = 1.f / su;
        Ps[r * 128 + j0] = e0 * inv; Ps[r * 128 + j1] = e1 * inv;
        Ps[r * 128 + j2] = e2 * inv; Ps[r * 128 + j3] = e3 * inv;
    }
    __syncthreads();
    for (int idx = tid; idx < 128 * 64; idx += 256) {
        int j = idx >> 6, d = idx & 63;
        int p = i0 - 64 + j;
        Ks[j * 65 + d] = (p >= 0)
            ? g_qkv[(size_t)p * QKVW_ + (H_ + KVH_) * D_ + kh * D_ + d] : 0.f;
    }
    __syncthreads();
#pragma unroll
    for (int rr = 0; rr < 8; rr++) {
        int r = w * 8 + rr;
        float a0 = 0.f, a1 = 0.f;
        for (int j = 0; j < 128; j++) {
            float p = Ps[r * 128 + j];
            a0 += p * Ks[j * 65 + lane];
            a1 += p * Ks[j * 65 + lane + 32];
        }
        size_t ob = ((size_t)h * N_ + i0 + r) * D_;
        g_sout[ob + lane] = a0;
        g_sout[ob + lane + 32] = a1;
    }
}

// ---------------- gated combine ----------------------------------------------
__global__ void combine_kernel() {
    int idx = blockIdx.x * blockDim.x + threadIdx.x;  // N*H*D
    if (idx >= N_ * H_ * D_) return;
    int d = idx % D_;
    int h = (idx / D_) % H_;
    int n = idx / (D_ * H_);
    const float* g = g_gates + ((size_t)n * H_ + h) * 3;
    size_t hnd = ((size_t)h * N_ + n) * D_ + d;
    g_comb[(size_t)n * DIM_ + h * D_ + d] =
        g[0] * g_cout[hnd] + g[1] * g_fout[hnd] + g[2] * g_sout[hnd];
}

// ---------------- launch -----------------------------------------------------
extern "C" void kernel_launch(void* const* d_in, const int* in_sizes, int n_in,
                              void* d_out, int out_size) {
    const float* inp    = (const float*)d_in[0];
    const float* norm_g = (const float*)d_in[1];
    const float* Wqkv   = (const float*)d_in[2];
    const float* mem_kv = (const float*)d_in[3];
    const float* k_pos  = (const float*)d_in[4];
    const float* v_pos  = (const float*)d_in[5];
    const float* kW1    = (const float*)d_in[6];
    const float* kb1    = (const float*)d_in[7];
    const float* kW2    = (const float*)d_in[8];
    const float* kb2    = (const float*)d_in[9];
    const float* vW1    = (const float*)d_in[10];
    const float* vb1    = (const float*)d_in[11];
    const float* vW2    = (const float*)d_in[12];
    const float* vb2    = (const float*)d_in[13];
    const float* combW  = (const float*)d_in[14];
    const float* combB  = (const float*)d_in[15];
    const float* Wout   = (const float*)d_in[16];
    float* out = (float*)d_out;

    float* px;     cudaGetSymbolAddress((void**)&px, g_x);
    float* pqkv;   cudaGetSymbolAddress((void**)&pqkv, g_qkv);
    float* pkw;    cudaGetSymbolAddress((void**)&pkw, g_kwflat);
    float* pvw;    cudaGetSymbolAddress((void**)&pvw, g_vwflat);
    float* ph1;    cudaGetSymbolAddress((void**)&ph1, g_h1);
    float* pckr;   cudaGetSymbolAddress((void**)&pckr, g_ckraw);
    float* pcvr;   cudaGetSymbolAddress((void**)&pcvr, g_cvraw);
    float* pckT;   cudaGetSymbolAddress((void**)&pckT, g_ckT);
    float* pcvp;   cudaGetSymbolAddress((void**)&pcvp, g_cvpad);
    float* pqc;    cudaGetSymbolAddress((void**)&pqc, g_qc);
    float* pcsim;  cudaGetSymbolAddress((void**)&pcsim, g_csim);
    float* pcout;  cudaGetSymbolAddress((void**)&pcout, g_cout);
    float* ppart;  cudaGetSymbolAddress((void**)&ppart, g_part);
    float* pgates; cudaGetSymbolAddress((void**)&pgates, g_gates);
    float* pcomb;  cudaGetSymbolAddress((void**)&pcomb, g_comb);

    static int smem_set = 0;
    const int SATTN_SMEM = (128 * 65 + 64 * 65 + 64 * 128) * 4;
    if (!smem_set) {
        cudaFuncSetAttribute(sattn_kernel, cudaFuncAttributeMaxDynamicSharedMemorySize, SATTN_SMEM);
        smem_set = 1;
    }

    // 1. RMSNorm
    rmsnorm_kernel<<<N_, 256>>>(inp, norm_g);
    // 2. qkv = x @ Wqkv  (2048x2048x1024, FFMA2)
    sgemm2_kernel<0, false><<<dim3(QKVW_ / 128, N_ / 64), 256>>>(px, DIM_, Wqkv, QKVW_,
                                                                 nullptr, pqkv, QKVW_,
                                                                 N_, QKVW_, DIM_);
    // 3. windows + rope/qc
    build_windows_kernel<<<(KVH_ * NCB_ * CBS_ * D_ + 255) / 256, 256>>>(k_pos, v_pos);
    rope_kernel<<<((H_ + KVH_) * N_ * (D_ / 2) + 255) / 256, 256>>>();
    // 4. compression MLPs (W1 FFMA2; W2 via split-K x4)
    sgemm2_kernel<1, true><<<dim3(HID_ / 128, (KVH_ * NCB_) / 64), 256>>>(
        pkw, HID_, kW1, HID_, kb1, ph1, HID_, KVH_ * NCB_, HID_, HID_);
    sgemm_kernel<0, false><<<dim3(1, 16, 4), 256>>>(ph1, HID_, 512, kW2, D_, (long)512 * D_,
                                                    nullptr, ppart, D_, (long)1024 * D_,
                                                    KVH_ * NCB_, D_, 512);
    reduce4_kernel<0><<<(1024 * D_ + 255) / 256, 256>>>(ppart, kb2, pckr, 1024 * D_, D_);
    sgemm2_kernel<1, true><<<dim3(HID_ / 128, (KVH_ * NCB_) / 64), 256>>>(
        pvw, HID_, vW1, HID_, vb1, ph1, HID_, KVH_ * NCB_, HID_, HID_);
    sgemm_kernel<0, false><<<dim3(1, 16, 4), 256>>>(ph1, HID_, 512, vW2, D_, (long)512 * D_,
                                                    nullptr, ppart, D_, (long)1024 * D_,
                                                    KVH_ * NCB_, D_, 512);
    reduce4_kernel<0><<<(1024 * D_ + 255) / 256, 256>>>(ppart, vb2, pcvr, 1024 * D_, D_);
    // 5. assemble ckT / cvpad
    assemble_c_kernel<<<(KVH_ * CJP_ * D_ + 255) / 256, 256>>>(mem_kv);
    // 6. compressed attention as batched GEMMs + softmax
    sgemm_kernel<0, false><<<dim3(3, 64, KVH_), 256>>>(
        pqc, D_, (long)(GQ_ * N_) * D_, pckT, CJP_, (long)D_ * CJP_, nullptr,
        pcsim, CJP_, (long)(GQ_ * N_) * CJP_, GQ_ * N_, CJ_, D_);
    importance_kernel<<<(KVH_ * N_ * NFB_ + 255) / 256, 256>>>();
    csoftmax_kernel<<<KVH_ * GQ_ * N_ / 8, 256>>>();
    sgemm_kernel<0, false><<<dim3(1, 64, KVH_), 256>>>(
        pcsim, CJP_, (long)(GQ_ * N_) * CJP_, pcvp, D_, (long)CJP_ * D_, nullptr,
        pcout, D_, (long)(GQ_ * N_) * D_, GQ_ * N_, D_, CJP_);
    // 7. top-k + fine attention
    topk_kernel<<<KVH_ * N_ / 8, 256>>>();
    fattn_kernel<<<KVH_ * N_, 160>>>();
    // 8. sliding-window attention (tiled)
    sattn_kernel<<<dim3(N_ / 64, H_), 256, SATTN_SMEM>>>();
    // 9. gates (split-K x4) + combine + output
    sgemm_kernel<0, false><<<dim3(1, 32, 4), 256>>>(px, DIM_, 256, combW, 48, (long)256 * 48,
                                                    nullptr, ppart, 48, (long)N_ * 48,
                                                    N_, 48, 256);
    reduce4_kernel<2><<<(N_ * 48 + 255) / 256, 256>>>(ppart, combB, pgates, N_ * 48, 48);
    combine_kernel<<<(N_ * H_ * D_ + 255) / 256, 256>>>();
    // 10. out = comb @ Wout (FFMA2)
    sgemm2_kernel<0, false><<<dim3(DIM_ / 128, N_ / 64), 256>>>(pcomb, DIM_, Wout, DIM_,
                                                                nullptr, out, DIM_,
                                                                N_, DIM_, DIM_);
}

// round 4
// speedup vs baseline: 1.3694x; 1.3694x over previous
#include <cuda_runtime.h>
#include <math.h>
#include <float.h>

#define N_      2048
#define DIM_    1024
#define H_      16
#define KVH_    8
#define GQ_     2
#define D_      64
#define WS_     64
#define CBS_    32
#define STRIDE_ 16
#define SEL_BLK_ 32
#define NSEL_   4
#define NMEM_   1
#define NCB_    128
#define NFB_    64
#define HID_    2048
#define SCALE_  0.125f
#define QKVW_   2048            /* (H + 2*KVH) * D */
#define CJ_     (NMEM_ + NCB_)  /* 129 */
#define CJP_    144             /* CJ padded to mult of 16 */

// ---------------- scratch (static device allocations) -----------------------
__device__ float g_x[N_ * DIM_];
__device__ float g_qkv[N_ * QKVW_];
__device__ float g_kwflat[KVH_ * NCB_ * HID_];
__device__ float g_vwflat[KVH_ * NCB_ * HID_];
__device__ float g_h1[KVH_ * NCB_ * HID_];
__device__ float g_ckraw[KVH_ * NCB_ * D_];
__device__ float g_cvraw[KVH_ * NCB_ * D_];
__device__ float g_ckT[KVH_ * D_ * CJP_];     // [kh][d][jp]
__device__ float g_cvpad[KVH_ * CJP_ * D_];   // [kh][jp][d], pad rows zero
__device__ float g_qc[H_ * N_ * D_];          // non-rope q, [h][n][d]
__device__ float g_csim[KVH_ * (GQ_ * N_) * CJP_];
__device__ float g_rq[H_ * N_ * D_];
__device__ float g_rk[KVH_ * N_ * D_];
__device__ float g_cout[H_ * N_ * D_];
__device__ float g_fout[H_ * N_ * D_];
__device__ float g_sout[H_ * N_ * D_];
__device__ float g_imp[KVH_ * N_ * NFB_];
__device__ int   g_selidx[KVH_ * N_ * 5];
__device__ int   g_selflag[KVH_ * N_ * 4];
__device__ float g_gates[N_ * H_ * 3];
__device__ float g_comb[N_ * DIM_];
__device__ float g_part[4 * N_ * 64];         // split-K partials (max use)

// ---------------- RMSNorm ---------------------------------------------------
__global__ void rmsnorm_kernel(const float* __restrict__ inp,
                               const float* __restrict__ gamma) {
    int row = blockIdx.x;
    const float* r = inp + (size_t)row * DIM_;
    float s = 0.f;
    for (int j = threadIdx.x; j < DIM_; j += blockDim.x) { float v = r[j]; s += v * v; }
    __shared__ float sh[32];
    for (int o = 16; o; o >>= 1) s += __shfl_down_sync(0xffffffffu, s, o);
    if ((threadIdx.x & 31) == 0) sh[threadIdx.x >> 5] = s;
    __syncthreads();
    if (threadIdx.x < 32) {
        s = (threadIdx.x < (blockDim.x >> 5)) ? sh[threadIdx.x] : 0.f;
        for (int o = 16; o; o >>= 1) s += __shfl_down_sync(0xffffffffu, s, o);
        if (threadIdx.x == 0) sh[0] = rsqrtf(s / (float)DIM_ + 1.1920929e-07f);
    }
    __syncthreads();
    float rs = sh[0];
    for (int j = threadIdx.x; j < DIM_; j += blockDim.x)
        g_x[(size_t)row * DIM_ + j] = r[j] * rs * gamma[j];
}

// ---------------- SGEMM128: 128x128 tile, BK=8, 8x8/thr, double-buffered ----
// A (M,K) lda, B (K,N) ldb row-major. Requires M%128==0, N%128==0, K%8==0.
template <int ACT, bool BIAS>
__global__ __launch_bounds__(256, 2)
void sgemm128_kernel(const float* __restrict__ A, int lda,
                     const float* __restrict__ B, int ldb,
                     const float* __restrict__ bias,
                     float* __restrict__ C, int ldc,
                     int M, int Ncols, int K) {
    __shared__ float As[2][8][128];
    __shared__ float Bs[2][8][128];
    const int bm = blockIdx.y * 128, bn = blockIdx.x * 128;
    const int tid = threadIdx.x;
    const int tx = tid & 15, ty = tid >> 4;        // 8-col group / 8-row group
    const int arow = tid >> 1, acol = (tid & 1) << 2;
    const int brow = tid >> 5, bcol = (tid & 31) << 2;
    const float* Aptr = A + (size_t)(bm + arow) * lda + acol;
    const float* Bptr = B + (size_t)brow * ldb + bn + bcol;

    float4 ar = *(const float4*)Aptr;
    float4 br = *(const float4*)Bptr;
    As[0][acol + 0][arow] = ar.x; As[0][acol + 1][arow] = ar.y;
    As[0][acol + 2][arow] = ar.z; As[0][acol + 3][arow] = ar.w;
    *(float4*)&Bs[0][brow][bcol] = br;
    __syncthreads();

    float acc[8][8];
#pragma unroll
    for (int i = 0; i < 8; i++)
#pragma unroll
        for (int j = 0; j < 8; j++) acc[i][j] = 0.f;

    const int nt = K >> 3;
    for (int t = 0; t < nt; t++) {
        const int cur = t & 1, nxt = cur ^ 1;
        if (t + 1 < nt) {
            ar = *(const float4*)(Aptr + (t + 1) * 8);
            br = *(const float4*)(Bptr + (size_t)(t + 1) * 8 * ldb);
        }
#pragma unroll
        for (int k = 0; k < 8; k++) {
            float4 a0 = *(const float4*)&As[cur][k][ty * 8];
            float4 a1 = *(const float4*)&As[cur][k][ty * 8 + 4];
            float4 b0 = *(const float4*)&Bs[cur][k][tx * 8];
            float4 b1 = *(const float4*)&Bs[cur][k][tx * 8 + 4];
            float a[8] = {a0.x, a0.y, a0.z, a0.w, a1.x, a1.y, a1.z, a1.w};
            float b[8] = {b0.x, b0.y, b0.z, b0.w, b1.x, b1.y, b1.z, b1.w};
#pragma unroll
            for (int i = 0; i < 8; i++)
#pragma unroll
                for (int j = 0; j < 8; j++) acc[i][j] += a[i] * b[j];
        }
        if (t + 1 < nt) {
            As[nxt][acol + 0][arow] = ar.x; As[nxt][acol + 1][arow] = ar.y;
            As[nxt][acol + 2][arow] = ar.z; As[nxt][acol + 3][arow] = ar.w;
            *(float4*)&Bs[nxt][brow][bcol] = br;
        }
        __syncthreads();
    }

#pragma unroll
    for (int i = 0; i < 8; i++) {
        int r = bm + ty * 8 + i;
        float* crow = C + (size_t)r * ldc + bn + tx * 8;
#pragma unroll
        for (int jj = 0; jj < 2; jj++) {
            float4 v;
            v.x = acc[i][jj * 4 + 0]; v.y = acc[i][jj * 4 + 1];
            v.z = acc[i][jj * 4 + 2]; v.w = acc[i][jj * 4 + 3];
            if (BIAS) {
                const float* bp = bias + bn + tx * 8 + jj * 4;
                v.x += bp[0]; v.y += bp[1]; v.z += bp[2]; v.w += bp[3];
            }
            if (ACT == 1) {
                v.x = fmaxf(v.x, 0.f); v.y = fmaxf(v.y, 0.f);
                v.z = fmaxf(v.z, 0.f); v.w = fmaxf(v.w, 0.f);
            }
            *(float4*)(crow + jj * 4) = v;
        }
    }
}

// ---------------- SGEMM (generalized, 64x64; for narrow/odd shapes) ---------
template <int ACT, bool BIAS>
__global__ void sgemm_kernel(const float* __restrict__ A, int lda, long sA,
                             const float* __restrict__ B, int ldb, long sB,
                             const float* __restrict__ bias,
                             float* __restrict__ C, int ldc, long sC,
                             int M, int Ncols, int K) {
    __shared__ float As[16][68];
    __shared__ float Bs[16][64];
    A += (size_t)blockIdx.z * sA;
    B += (size_t)blockIdx.z * sB;
    C += (size_t)blockIdx.z * sC;
    const int bm = blockIdx.y * 64, bn = blockIdx.x * 64;
    const int tid = threadIdx.x;
    const int tx = tid & 15, ty = tid >> 4;
    const int arow = tid >> 2, acol4 = (tid & 3) << 2;
    const int brow = tid >> 4, bcol4 = (tid & 15) << 2;
    float acc[4][4] = {};
    for (int k0 = 0; k0 < K; k0 += 16) {
        float4 av = make_float4(0.f, 0.f, 0.f, 0.f);
        if (bm + arow < M)
            av = *(const float4*)(A + (size_t)(bm + arow) * lda + k0 + acol4);
        As[acol4 + 0][arow] = av.x; As[acol4 + 1][arow] = av.y;
        As[acol4 + 2][arow] = av.z; As[acol4 + 3][arow] = av.w;
        float4 bv = make_float4(0.f, 0.f, 0.f, 0.f);
        if (bn + bcol4 < Ncols)
            bv = *(const float4*)(B + (size_t)(k0 + brow) * ldb + bn + bcol4);
        *(float4*)&Bs[brow][bcol4] = bv;
        __syncthreads();
#pragma unroll
        for (int k = 0; k < 16; k++) {
            float a[4], b[4];
#pragma unroll
            for (int i = 0; i < 4; i++) a[i] = As[k][ty * 4 + i];
#pragma unroll
            for (int j = 0; j < 4; j++) b[j] = Bs[k][tx * 4 + j];
#pragma unroll
            for (int i = 0; i < 4; i++)
#pragma unroll
                for (int j = 0; j < 4; j++) acc[i][j] += a[i] * b[j];
        }
        __syncthreads();
    }
#pragma unroll
    for (int i = 0; i < 4; i++) {
        int r = bm + ty * 4 + i;
        if (r >= M) continue;
#pragma unroll
        for (int j = 0; j < 4; j++) {
            int c = bn + tx * 4 + j;
            if (c >= Ncols) continue;
            float v = acc[i][j];
            if (BIAS) v += bias[c];
            if (ACT == 1) v = fmaxf(v, 0.f);
            C[(size_t)r * ldc + c] = v;
        }
    }
}

// ---------------- split-K reduce (Z=4) ---------------------------------------
template <int ACT>
__global__ void reduce4_kernel(const float* __restrict__ part,
                               const float* __restrict__ bias,
                               float* __restrict__ out, int total, int ncols) {
    int idx = blockIdx.x * blockDim.x + threadIdx.x;
    if (idx >= total) return;
    float v = part[idx] + part[idx + total] + part[idx + 2 * total] +
              part[idx + 3 * total] + bias[idx % ncols];
    if (ACT == 2) v = 1.f / (1.f + expf(-v));
    out[idx] = v;
}

// ---------------- build compression windows ---------------------------------
__global__ void build_windows_kernel(const float* __restrict__ k_pos,
                                     const float* __restrict__ v_pos) {
    int idx = blockIdx.x * blockDim.x + threadIdx.x;
    if (idx >= KVH_ * NCB_ * CBS_ * D_) return;
    int d  = idx % D_;
    int t  = (idx / D_) % CBS_;
    int c  = (idx / (D_ * CBS_)) % NCB_;
    int kh = idx / (D_ * CBS_ * NCB_);
    int pos = c * STRIDE_ + t - (CBS_ - STRIDE_);
    float kv = 0.f, vv = 0.f;
    if (pos >= 0) {
        kv = g_qkv[(size_t)pos * QKVW_ + H_ * D_ + kh * D_ + d];
        vv = g_qkv[(size_t)pos * QKVW_ + (H_ + KVH_) * D_ + kh * D_ + d];
    }
    kv += k_pos[(kh * CBS_ + t) * D_ + d];
    vv += v_pos[(kh * CBS_ + t) * D_ + d];
    size_t row = (size_t)kh * NCB_ + c;
    g_kwflat[row * HID_ + t * D_ + d] = kv;
    g_vwflat[row * HID_ + t * D_ + d] = vv;
}

// ---------------- assemble ckT / cvpad ---------------------------------------
__global__ void assemble_c_kernel(const float* __restrict__ mem_kv) {
    int idx = blockIdx.x * blockDim.x + threadIdx.x;
    if (idx >= KVH_ * CJP_ * D_) return;
    int d  = idx % D_;
    int j  = (idx / D_) % CJP_;
    int kh = idx / (D_ * CJP_);
    float kvv = 0.f, vvv = 0.f;
    if (j < NMEM_) {
        kvv = mem_kv[((0 * KVH_ + kh) * NMEM_ + j) * D_ + d];
        vvv = mem_kv[((1 * KVH_ + kh) * NMEM_ + j) * D_ + d];
    } else if (j < CJ_) {
        kvv = g_ckraw[((size_t)kh * NCB_ + (j - NMEM_)) * D_ + d];
        vvv = g_cvraw[((size_t)kh * NCB_ + (j - NMEM_)) * D_ + d];
    }
    g_ckT[((size_t)kh * D_ + d) * CJP_ + j] = kvv;
    g_cvpad[((size_t)kh * CJP_ + j) * D_ + d] = vvv;
}

// ---------------- RoPE (+ extract non-rope q) --------------------------------
__global__ void rope_kernel() {
    int idx = blockIdx.x * blockDim.x + threadIdx.x;
    if (idx >= (H_ + KVH_) * N_ * (D_ / 2)) return;
    int m = idx % (D_ / 2);
    int n = (idx / (D_ / 2)) % N_;
    int h = idx / ((D_ / 2) * N_);
    float inv = exp2f(-(float)m * (2.0f / (float)D_) * 13.2877123795f);
    float ang = (float)n * inv;
    float c = cosf(ang), s = sinf(ang);
    const float* src;
    float* dst;
    if (h < H_) {
        src = g_qkv + (size_t)n * QKVW_ + h * D_;
        dst = g_rq + ((size_t)h * N_ + n) * D_;
    } else {
        int kh = h - H_;
        src = g_qkv + (size_t)n * QKVW_ + H_ * D_ + kh * D_;
        dst = g_rk + ((size_t)kh * N_ + n) * D_;
    }
    float a = src[2 * m], b = src[2 * m + 1];
    dst[2 * m]     = a * c - b * s;
    dst[2 * m + 1] = b * c + a * s;
    if (h < H_) {
        float* qd = g_qc + ((size_t)h * N_ + n) * D_;
        qd[2 * m] = a; qd[2 * m + 1] = b;
    }
}

// ---------------- importance (pre-softmax csim) ------------------------------
__global__ void importance_kernel() {
    int idx = blockIdx.x * blockDim.x + threadIdx.x;  // KVH*N*NFB
    if (idx >= KVH_ * N_ * NFB_) return;
    int fb = idx % NFB_;
    int i  = (idx / NFB_) % N_;
    int kh = idx / (NFB_ * N_);
    const float* base = g_csim + (size_t)kh * (GQ_ * N_) * CJP_;
    int c = NMEM_ + 2 * fb;
    float v = base[(size_t)i * CJP_ + c] + base[(size_t)i * CJP_ + c + 1] +
              base[(size_t)(N_ + i) * CJP_ + c] + base[(size_t)(N_ + i) * CJP_ + c + 1];
    g_imp[((size_t)kh * N_ + i) * NFB_ + fb] = 0.25f * SCALE_ * v;
}

// ---------------- compressed softmax (in-place, warp per row) ----------------
__global__ void csoftmax_kernel() {
    int row  = blockIdx.x * 8 + (threadIdx.x >> 5);  // 0..KVH*GQ*N-1
    int lane = threadIdx.x & 31;
    float* p = g_csim + (size_t)row * CJP_;
    float v0 = p[lane] * SCALE_, v1 = p[lane + 32] * SCALE_;
    float v2 = p[lane + 64] * SCALE_, v3 = p[lane + 96] * SCALE_;
    float v4 = (lane == 0) ? p[128] * SCALE_ : -FLT_MAX;
    float m = fmaxf(fmaxf(fmaxf(v0, v1), fmaxf(v2, v3)), v4);
    for (int o = 16; o; o >>= 1) m = fmaxf(m, __shfl_xor_sync(0xffffffffu, m, o));
    float e0 = expf(v0 - m), e1 = expf(v1 - m), e2 = expf(v2 - m), e3 = expf(v3 - m);
    float e4 = (lane == 0) ? expf(v4 - m) : 0.f;
    float s = e0 + e1 + e2 + e3 + e4;
    for (int o = 16; o; o >>= 1) s += __shfl_xor_sync(0xffffffffu, s, o);
    float inv = 1.f / s;
    p[lane] = e0 * inv; p[lane + 32] = e1 * inv;
    p[lane + 64] = e2 * inv; p[lane + 96] = e3 * inv;
    if (lane == 0) p[128] = e4 * inv;
    if (lane >= 1 && lane < 16) p[128 + lane] = 0.f;  // zero pad cols
}

// ---------------- top-k (warp per row) ----------------------------------------
__global__ void topk_kernel() {
    int row  = blockIdx.x * 8 + (threadIdx.x >> 5);  // KVH*N rows
    int lane = threadIdx.x & 31;
    int i = row & (N_ - 1);
    int qb = i >> 5;
    const float* ip = g_imp + (size_t)row * NFB_;
    float v0 = (lane == qb)      ? -FLT_MAX : ip[lane];
    float v1 = (lane + 32 == qb) ? -FLT_MAX : ip[lane + 32];
    float m = fmaxf(fmaxf(v0, v1), -1000.f);
    for (int o = 16; o; o >>= 1) m = fmaxf(m, __shfl_xor_sync(0xffffffffu, m, o));
    float s = expf(v0 - m) + expf(v1 - m);
    for (int o = 16; o; o >>= 1) s += __shfl_xor_sync(0xffffffffu, s, o);
    s += expf(-1000.f - m);
    float inv = 1.f / s;
    float p0 = expf(v0 - m) * inv, p1 = expf(v1 - m) * inv;
#pragma unroll
    for (int sel = 0; sel < NSEL_; sel++) {
        float bv; int bi;
        if (p0 >= p1) { bv = p0; bi = lane; } else { bv = p1; bi = lane + 32; }
        for (int o = 16; o; o >>= 1) {
            float ov = __shfl_xor_sync(0xffffffffu, bv, o);
            int   oi = __shfl_xor_sync(0xffffffffu, bi, o);
            if (ov > bv || (ov == bv && oi < bi)) { bv = ov; bi = oi; }
        }
        if (lane == 0) {
            g_selidx[(size_t)row * 5 + sel] = bi;
            g_selflag[(size_t)row * 4 + sel] = (bv > 1e-10f) ? 1 : 0;
        }
        if (bi == lane) p0 = -1.f;
        if (bi == lane + 32) p1 = -1.f;
    }
    if (lane == 0) g_selidx[(size_t)row * 5 + 4] = qb;
}

// ---------------- fine attention (warp-per-keygroup QK) ----------------------
__global__ void fattn_kernel() {
    int i  = blockIdx.x & (N_ - 1);
    int kh = blockIdx.x >> 11;
    __shared__ float qs[2][D_];
    __shared__ float sims[2][5 * SEL_BLK_];
    __shared__ int   sblk[5];
    __shared__ int   sfl[5];
    __shared__ float red[2][2];
    int tid = threadIdx.x;  // 160 = 5 warps
    int w = tid >> 5, lane = tid & 31;
    if (tid < 5) {
        sblk[tid] = g_selidx[((size_t)kh * N_ + i) * 5 + tid];
        sfl[tid]  = (tid < 4) ? g_selflag[((size_t)kh * N_ + i) * 4 + tid] : 1;
    }
    if (tid < 128) {
        int g = tid >> 6, d = tid & 63;
        qs[g][d] = g_rq[(((size_t)(kh * GQ_ + g)) * N_ + i) * D_ + d];
    }
    __syncthreads();
    {
        float q0a = qs[0][lane], q0b = qs[0][lane + 32];
        float q1a = qs[1][lane], q1b = qs[1][lane + 32];
        int blk = sblk[w];
        bool grpvalid = (w < 4) ? (sfl[w] != 0) : true;
        int lim = (w == 4) ? (i & 31) : 31;
        const float* kbase = g_rk + ((size_t)kh * N_ + blk * SEL_BLK_) * D_;
        for (int kk = 0; kk < SEL_BLK_; kk++) {
            float s0 = -FLT_MAX / 10.f, s1 = -FLT_MAX / 10.f;
            if (grpvalid && kk <= lim) {
                float ka = kbase[kk * D_ + lane], kb = kbase[kk * D_ + lane + 32];
                float p0 = q0a * ka + q0b * kb;
                float p1 = q1a * ka + q1b * kb;
                for (int o = 16; o; o >>= 1) {
                    p0 += __shfl_xor_sync(0xffffffffu, p0, o);
                    p1 += __shfl_xor_sync(0xffffffffu, p1, o);
                }
                s0 = p0 * SCALE_; s1 = p1 * SCALE_;
            }
            if (lane == 0) { sims[0][w * 32 + kk] = s0; sims[1][w * 32 + kk] = s1; }
        }
    }
    __syncthreads();
    if (tid < 64) {
        int g = tid >> 5, l = tid & 31;
        float m = -FLT_MAX;
        for (int j = l; j < 160; j += 32) m = fmaxf(m, sims[g][j]);
        for (int o = 16; o; o >>= 1) m = fmaxf(m, __shfl_xor_sync(0xffffffffu, m, o));
        float sm = 0.f;
        for (int j = l; j < 160; j += 32) sm += expf(sims[g][j] - m);
        for (int o = 16; o; o >>= 1) sm += __shfl_xor_sync(0xffffffffu, sm, o);
        if (l == 0) { red[g][0] = m; red[g][1] = sm; }
    }
    __syncthreads();
    for (int j = tid; j < 320; j += 160) {
        int g = j / 160, jj = j % 160;
        sims[g][jj] = expf(sims[g][jj] - red[g][0]) / red[g][1];
    }
    __syncthreads();
    if (tid < 128) {
        int g = tid >> 6, d = tid & 63;
        const float* vbase = g_qkv + (size_t)(H_ + KVH_) * D_ + kh * D_ + d;
        float acc = 0.f;
#pragma unroll
        for (int s = 0; s < 5; s++) {
            int pb = sblk[s] * SEL_BLK_;
#pragma unroll 8
            for (int t = 0; t < SEL_BLK_; t++)
                acc += sims[g][s * 32 + t] * vbase[(size_t)(pb + t) * QKVW_];
        }
        g_fout[(((size_t)(kh * GQ_ + g)) * N_ + i) * D_ + d] = acc;
    }
}

// ---------------- sliding-window attention (tiled, smem) ---------------------
__global__ void sattn_kernel() {
    extern __shared__ float sm[];
    float* Ks = sm;                        // 128 x 65
    float* Qs = sm + 128 * 65;             // 64 x 65
    float* Ps = Qs + 64 * 65;              // 64 x 128
    int tIdx = blockIdx.x, h = blockIdx.y, kh = h >> 1;
    int i0 = tIdx * 64;
    int tid = threadIdx.x, w = tid >> 5, lane = tid & 31;
    for (int idx = tid; idx < 64 * 64; idx += 256) {
        int r = idx >> 6, d = idx & 63;
        Qs[r * 65 + d] = g_rq[((size_t)h * N_ + i0 + r) * D_ + d];
    }
    for (int idx = tid; idx < 128 * 64; idx += 256) {
        int j = idx >> 6, d = idx & 63;
        int p = i0 - 64 + j;
        Ks[j * 65 + d] = (p >= 0) ? g_rk[((size_t)kh * N_ + p) * D_ + d] : 0.f;
    }
    __syncthreads();
#pragma unroll
    for (int rr = 0; rr < 8; rr++) {
        int r = w * 8 + rr;
        int j0 = lane, j1 = lane + 32, j2 = lane + 64, j3 = lane + 96;
        float a0 = 0.f, a1 = 0.f, a2 = 0.f, a3 = 0.f;
        for (int d = 0; d < 64; d++) {
            float q = Qs[r * 65 + d];
            a0 += q * Ks[j0 * 65 + d]; a1 += q * Ks[j1 * 65 + d];
            a2 += q * Ks[j2 * 65 + d]; a3 += q * Ks[j3 * 65 + d];
        }
        float s0, s1, s2, s3;
        {
            bool ok;
            ok = (j0 >= r + 1) && (j0 <= r + 64) && (i0 - 64 + j0 >= 0);
            s0 = ok ? a0 * SCALE_ : -FLT_MAX;
            ok = (j1 >= r + 1) && (j1 <= r + 64) && (i0 - 64 + j1 >= 0);
            s1 = ok ? a1 * SCALE_ : -FLT_MAX;
            ok = (j2 >= r + 1) && (j2 <= r + 64) && (i0 - 64 + j2 >= 0);
            s2 = ok ? a2 * SCALE_ : -FLT_MAX;
            ok = (j3 >= r + 1) && (j3 <= r + 64) && (i0 - 64 + j3 >= 0);
            s3 = ok ? a3 * SCALE_ : -FLT_MAX;
        }
        float m = fmaxf(fmaxf(s0, s1), fmaxf(s2, s3));
        for (int o = 16; o; o >>= 1) m = fmaxf(m, __shfl_xor_sync(0xffffffffu, m, o));
        float e0 = expf(s0 - m), e1 = expf(s1 - m), e2 = expf(s2 - m), e3 = expf(s3 - m);
        float su = e0 + e1 + e2 + e3;
        for (int o = 16; o; o >>= 1) su += __shfl_xor_sync(0xffffffffu, su, o);
        float inv = 1.f / su;
        Ps[r * 128 + j0] = e0 * inv; Ps[r * 128 + j1] = e1 * inv;
        Ps[r * 128 + j2] = e2 * inv; Ps[r * 128 + j3] = e3 * inv;
    }
    __syncthreads();
    for (int idx = tid; idx < 128 * 64; idx += 256) {
        int j = idx >> 6, d = idx & 63;
        int p = i0 - 64 + j;
        Ks[j * 65 + d] = (p >= 0)
            ? g_qkv[(size_t)p * QKVW_ + (H_ + KVH_) * D_ + kh * D_ + d] : 0.f;
    }
    __syncthreads();
#pragma unroll
    for (int rr = 0; rr < 8; rr++) {
        int r = w * 8 + rr;
        float a0 = 0.f, a1 = 0.f;
        for (int j = 0; j < 128; j++) {
            float p = Ps[r * 128 + j];
            a0 += p * Ks[j * 65 + lane];
            a1 += p * Ks[j * 65 + lane + 32];
        }
        size_t ob = ((size_t)h * N_ + i0 + r) * D_;
        g_sout[ob + lane] = a0;
        g_sout[ob + lane + 32] = a1;
    }
}

// ---------------- gated combine ----------------------------------------------
__global__ void combine_kernel() {
    int idx = blockIdx.x * blockDim.x + threadIdx.x;  // N*H*D
    if (idx >= N_ * H_ * D_) return;
    int d = idx % D_;
    int h = (idx / D_) % H_;
    int n = idx / (D_ * H_);
    const float* g = g_gates + ((size_t)n * H_ + h) * 3;
    size_t hnd = ((size_t)h * N_ + n) * D_ + d;
    g_comb[(size_t)n * DIM_ + h * D_ + d] =
        g[0] * g_cout[hnd] + g[1] * g_fout[hnd] + g[2] * g_sout[hnd];
}

// ---------------- launch -----------------------------------------------------
extern "C" void kernel_launch(void* const* d_in, const int* in_sizes, int n_in,
                              void* d_out, int out_size) {
    const float* inp    = (const float*)d_in[0];
    const float* norm_g = (const float*)d_in[1];
    const float* Wqkv   = (const float*)d_in[2];
    const float* mem_kv = (const float*)d_in[3];
    const float* k_pos  = (const float*)d_in[4];
    const float* v_pos  = (const float*)d_in[5];
    const float* kW1    = (const float*)d_in[6];
    const float* kb1    = (const float*)d_in[7];
    const float* kW2    = (const float*)d_in[8];
    const float* kb2    = (const float*)d_in[9];
    const float* vW1    = (const float*)d_in[10];
    const float* vb1    = (const float*)d_in[11];
    const float* vW2    = (const float*)d_in[12];
    const float* vb2    = (const float*)d_in[13];
    const float* combW  = (const float*)d_in[14];
    const float* combB  = (const float*)d_in[15];
    const float* Wout   = (const float*)d_in[16];
    float* out = (float*)d_out;

    float* px;     cudaGetSymbolAddress((void**)&px, g_x);
    float* pqkv;   cudaGetSymbolAddress((void**)&pqkv, g_qkv);
    float* pkw;    cudaGetSymbolAddress((void**)&pkw, g_kwflat);
    float* pvw;    cudaGetSymbolAddress((void**)&pvw, g_vwflat);
    float* ph1;    cudaGetSymbolAddress((void**)&ph1, g_h1);
    float* pckr;   cudaGetSymbolAddress((void**)&pckr, g_ckraw);
    float* pcvr;   cudaGetSymbolAddress((void**)&pcvr, g_cvraw);
    float* pckT;   cudaGetSymbolAddress((void**)&pckT, g_ckT);
    float* pcvp;   cudaGetSymbolAddress((void**)&pcvp, g_cvpad);
    float* pqc;    cudaGetSymbolAddress((void**)&pqc, g_qc);
    float* pcsim;  cudaGetSymbolAddress((void**)&pcsim, g_csim);
    float* pcout;  cudaGetSymbolAddress((void**)&pcout, g_cout);
    float* ppart;  cudaGetSymbolAddress((void**)&ppart, g_part);
    float* pgates; cudaGetSymbolAddress((void**)&pgates, g_gates);
    float* pcomb;  cudaGetSymbolAddress((void**)&pcomb, g_comb);

    const int SATTN_SMEM = (128 * 65 + 64 * 65 + 64 * 128) * 4;
    cudaFuncSetAttribute(sattn_kernel, cudaFuncAttributeMaxDynamicSharedMemorySize, SATTN_SMEM);

    // 1. RMSNorm
    rmsnorm_kernel<<<N_, 256>>>(inp, norm_g);
    // 2. qkv = x @ Wqkv (128x128 double-buffered)
    sgemm128_kernel<0, false><<<dim3(QKVW_ / 128, N_ / 128), 256>>>(
        px, DIM_, Wqkv, QKVW_, nullptr, pqkv, QKVW_, N_, QKVW_, DIM_);
    // 3. windows + rope/qc
    build_windows_kernel<<<(KVH_ * NCB_ * CBS_ * D_ + 255) / 256, 256>>>(k_pos, v_pos);
    rope_kernel<<<((H_ + KVH_) * N_ * (D_ / 2) + 255) / 256, 256>>>();
    // 4. compression MLPs (W1 128x128; W2 via split-K x4)
    sgemm128_kernel<1, true><<<dim3(HID_ / 128, (KVH_ * NCB_) / 128), 256>>>(
        pkw, HID_, kW1, HID_, kb1, ph1, HID_, KVH_ * NCB_, HID_, HID_);
    sgemm_kernel<0, false><<<dim3(1, 16, 4), 256>>>(ph1, HID_, 512, kW2, D_, (long)512 * D_,
                                                    nullptr, ppart, D_, (long)1024 * D_,
                                                    KVH_ * NCB_, D_, 512);
    reduce4_kernel<0><<<(1024 * D_ + 255) / 256, 256>>>(ppart, kb2, pckr, 1024 * D_, D_);
    sgemm128_kernel<1, true><<<dim3(HID_ / 128, (KVH_ * NCB_) / 128), 256>>>(
        pvw, HID_, vW1, HID_, vb1, ph1, HID_, KVH_ * NCB_, HID_, HID_);
    sgemm_kernel<0, false><<<dim3(1, 16, 4), 256>>>(ph1, HID_, 512, vW2, D_, (long)512 * D_,
                                                    nullptr, ppart, D_, (long)1024 * D_,
                                                    KVH_ * NCB_, D_, 512);
    reduce4_kernel<0><<<(1024 * D_ + 255) / 256, 256>>>(ppart, vb2, pcvr, 1024 * D_, D_);
    // 5. assemble ckT / cvpad
    assemble_c_kernel<<<(KVH_ * CJP_ * D_ + 255) / 256, 256>>>(mem_kv);
    // 6. compressed attention as batched GEMMs + softmax
    sgemm_kernel<0, false><<<dim3(3, 64, KVH_), 256>>>(
        pqc, D_, (long)(GQ_ * N_) * D_, pckT, CJP_, (long)D_ * CJP_, nullptr,
        pcsim, CJP_, (long)(GQ_ * N_) * CJP_, GQ_ * N_, CJ_, D_);
    importance_kernel<<<(KVH_ * N_ * NFB_ + 255) / 256, 256>>>();
    csoftmax_kernel<<<KVH_ * GQ_ * N_ / 8, 256>>>();
    sgemm_kernel<0, false><<<dim3(1, 64, KVH_), 256>>>(
        pcsim, CJP_, (long)(GQ_ * N_) * CJP_, pcvp, D_, (long)CJP_ * D_, nullptr,
        pcout, D_, (long)(GQ_ * N_) * D_, GQ_ * N_, D_, CJP_);
    // 7. top-k + fine attention
    topk_kernel<<<KVH_ * N_ / 8, 256>>>();
    fattn_kernel<<<KVH_ * N_, 160>>>();
    // 8. sliding-window attention (tiled)
    sattn_kernel<<<dim3(N_ / 64, H_), 256, SATTN_SMEM>>>();
    // 9. gates (split-K x4) + combine + output
    sgemm_kernel<0, false><<<dim3(1, 32, 4), 256>>>(px, DIM_, 256, combW, 48, (long)256 * 48,
                                                    nullptr, ppart, 48, (long)N_ * 48,
                                                    N_, 48, 256);
    reduce4_kernel<2><<<(N_ * 48 + 255) / 256, 256>>>(ppart, combB, pgates, N_ * 48, 48);
    combine_kernel<<<(N_ * H_ * D_ + 255) / 256, 256>>>();
    // 10. out = comb @ Wout (128x128)
    sgemm128_kernel<0, false><<<dim3(DIM_ / 128, N_ / 128), 256>>>(
        pcomb, DIM_, Wout, DIM_, nullptr, out, DIM_, N_, DIM_, DIM_);
}

// round 6
// speedup vs baseline: 2.0676x; 1.5099x over previous
#include <cuda_runtime.h>
#include <cuda_bf16.h>
#include <math.h>
#include <float.h>

#define N_      2048
#define DIM_    1024
#define H_      16
#define KVH_    8
#define GQ_     2
#define D_      64
#define WS_     64
#define CBS_    32
#define STRIDE_ 16
#define SEL_BLK_ 32
#define NSEL_   4
#define NMEM_   1
#define NCB_    128
#define NFB_    64
#define HID_    2048
#define SCALE_  0.125f
#define QKVW_   2048
#define CJ_     (NMEM_ + NCB_)
#define CJP_    144
#define PADK    40              /* 32 data + 8 pad bf16 per smem row */

// ---------------- scratch -----------------------------------------------------
__device__ float g_x[N_ * DIM_];
__device__ float g_qkv[N_ * QKVW_];
__device__ float g_kwflat[KVH_ * NCB_ * HID_];
__device__ float g_vwflat[KVH_ * NCB_ * HID_];
__device__ float g_h1[KVH_ * NCB_ * HID_];
__device__ float g_ckraw[KVH_ * NCB_ * D_];
__device__ float g_cvraw[KVH_ * NCB_ * D_];
__device__ float g_ckT[KVH_ * D_ * CJP_];
__device__ float g_cvpad[KVH_ * CJP_ * D_];
__device__ float g_qc[H_ * N_ * D_];
__device__ float g_csim[KVH_ * (GQ_ * N_) * CJP_];
__device__ float g_rq[H_ * N_ * D_];
__device__ float g_rk[KVH_ * N_ * D_];
__device__ float g_cout[H_ * N_ * D_];
__device__ float g_fout[H_ * N_ * D_];
__device__ float g_sout[H_ * N_ * D_];
__device__ float g_imp[KVH_ * N_ * NFB_];
__device__ int   g_selidx[KVH_ * N_ * 5];
__device__ int   g_selflag[KVH_ * N_ * 4];
__device__ float g_gates[N_ * H_ * 3];
__device__ float g_comb[N_ * DIM_];
__device__ float g_part[4 * N_ * 64];
__device__ __nv_bfloat16 g_ah[2 * 1024 * 1024];
__device__ __nv_bfloat16 g_al[2 * 1024 * 1024];
__device__ __nv_bfloat16 g_bh[4 * 1024 * 1024];
__device__ __nv_bfloat16 g_bl[4 * 1024 * 1024];

// ---------------- warp-MMA helpers (sm_80+ PTX, sm_103-safe) ------------------
__device__ __forceinline__ unsigned smem_u32(const void* p) {
    unsigned a;
    asm("{ .reg .u64 t; cvta.to.shared.u64 t, %1; cvt.u32.u64 %0, t; }"
        : "=r"(a) : "l"(p));
    return a;
}
__device__ __forceinline__ void ldm_x4(unsigned& r0, unsigned& r1,
                                       unsigned& r2, unsigned& r3, unsigned a) {
    asm volatile("ldmatrix.sync.aligned.m8n8.x4.shared.b16 {%0,%1,%2,%3}, [%4];"
                 : "=r"(r0), "=r"(r1), "=r"(r2), "=r"(r3) : "r"(a));
}
__device__ __forceinline__ void mma16816(float* c, const unsigned* a,
                                         const unsigned* b) {
    asm volatile(
        "mma.sync.aligned.m16n8k16.row.col.f32.bf16.bf16.f32 "
        "{%0,%1,%2,%3}, {%4,%5,%6,%7}, {%8,%9}, {%0,%1,%2,%3};"
        : "+f"(c[0]), "+f"(c[1]), "+f"(c[2]), "+f"(c[3])
        : "r"(a[0]), "r"(a[1]), "r"(a[2]), "r"(a[3]), "r"(b[0]), "r"(b[1]));
}

// ---------------- hi/lo split kernels ----------------------------------------
__global__ void split_kernel(const float* __restrict__ in, int total,
                             __nv_bfloat16* __restrict__ oh,
                             __nv_bfloat16* __restrict__ ol) {
    int idx = blockIdx.x * blockDim.x + threadIdx.x;
    if (idx >= total) return;
    float v = in[idx];
    __nv_bfloat16 h = __float2bfloat16(v);
    oh[idx] = h;
    ol[idx] = __float2bfloat16(v - __bfloat162float(h));
}

__global__ void transpose_split_kernel(const float* __restrict__ in, int R, int C,
                                       __nv_bfloat16* __restrict__ oh,
                                       __nv_bfloat16* __restrict__ ol) {
    __shared__ float t[32][33];
    int c0 = blockIdx.x * 32, r0 = blockIdx.y * 32;
    int tx = threadIdx.x, ty = threadIdx.y;
#pragma unroll
    for (int j = 0; j < 32; j += 8)
        t[ty + j][tx] = in[(size_t)(r0 + ty + j) * C + c0 + tx];
    __syncthreads();
#pragma unroll
    for (int j = 0; j < 32; j += 8) {
        float v = t[tx][ty + j];
        __nv_bfloat16 h = __float2bfloat16(v);
        size_t o = (size_t)(c0 + ty + j) * R + r0 + tx;
        oh[o] = h;
        ol[o] = __float2bfloat16(v - __bfloat162float(h));
    }
}

// ---------------- tensor-core GEMM via mma.sync (bf16 split, fp32 acc) -------
// A [M,K] bf16 hi/lo; B [N,K] bf16 hi/lo (pre-transposed). C = act(A·B^T + bias)
// CTA 128x128, BK=32, 8 warps (2m x 4n), warp tile 64x32.
template <int ACT, bool BIAS>
__global__ __launch_bounds__(256, 1)
void tcgemm_kernel(const __nv_bfloat16* __restrict__ Ah,
                   const __nv_bfloat16* __restrict__ Al,
                   const __nv_bfloat16* __restrict__ Bh,
                   const __nv_bfloat16* __restrict__ Bl,
                   const float* __restrict__ bias,
                   float* __restrict__ C, int ldc,
                   int M, int Ncols, int K) {
    __shared__ __nv_bfloat16 sAh[128 * PADK];
    __shared__ __nv_bfloat16 sAl[128 * PADK];
    __shared__ __nv_bfloat16 sBh[128 * PADK];
    __shared__ __nv_bfloat16 sBl[128 * PADK];
    const int tid = threadIdx.x;
    const int wid = tid >> 5, lane = tid & 31;
    const int bm = blockIdx.y * 128, bn = blockIdx.x * 128;
    const int wm = (wid & 1) * 64, wn = (wid >> 1) * 32;

    // global->smem mapping: thread handles rows r and r+64, 16B chunk c16
    const int r = tid >> 2, c16 = tid & 3;
    const unsigned sA_u = smem_u32(sAh), sAl_u = smem_u32(sAl);
    const unsigned sB_u = smem_u32(sBh), sBl_u = smem_u32(sBl);
    const unsigned soff0 = (r * PADK + c16 * 8) * 2;
    const unsigned soff1 = ((r + 64) * PADK + c16 * 8) * 2;

    float acc[4][4][4];
#pragma unroll
    for (int i = 0; i < 4; i++)
#pragma unroll
        for (int j = 0; j < 4; j++)
#pragma unroll
            for (int c = 0; c < 4; c++) acc[i][j][c] = 0.f;

    const int nt = K >> 5;
    uint4 pah0, pah1, pal0, pal1, pbh0, pbh1, pbl0, pbl1;
    {
        size_t gA = (size_t)(bm + r) * K + c16 * 8;
        size_t gB = (size_t)(bn + r) * K + c16 * 8;
        pah0 = *(const uint4*)(Ah + gA); pah1 = *(const uint4*)(Ah + gA + (size_t)64 * K);
        pal0 = *(const uint4*)(Al + gA); pal1 = *(const uint4*)(Al + gA + (size_t)64 * K);
        pbh0 = *(const uint4*)(Bh + gB); pbh1 = *(const uint4*)(Bh + gB + (size_t)64 * K);
        pbl0 = *(const uint4*)(Bl + gB); pbl1 = *(const uint4*)(Bl + gB + (size_t)64 * K);
    }
    *(uint4*)((char*)sAh + soff0) = pah0; *(uint4*)((char*)sAh + soff1) = pah1;
    *(uint4*)((char*)sAl + soff0) = pal0; *(uint4*)((char*)sAl + soff1) = pal1;
    *(uint4*)((char*)sBh + soff0) = pbh0; *(uint4*)((char*)sBh + soff1) = pbh1;
    *(uint4*)((char*)sBl + soff0) = pbl0; *(uint4*)((char*)sBl + soff1) = pbl1;
    __syncthreads();

    // ldmatrix per-lane offsets (byte units)
    const int a_row = (lane & 15), a_k8 = (lane >> 4) << 3;
    const int b_n = (lane & 7) + ((lane >> 4) << 3), b_k8 = (lane & 8);

    for (int t = 0; t < nt; t++) {
        if (t + 1 < nt) {
            size_t gA = (size_t)(bm + r) * K + (t + 1) * 32 + c16 * 8;
            size_t gB = (size_t)(bn + r) * K + (t + 1) * 32 + c16 * 8;
            pah0 = *(const uint4*)(Ah + gA); pah1 = *(const uint4*)(Ah + gA + (size_t)64 * K);
            pal0 = *(const uint4*)(Al + gA); pal1 = *(const uint4*)(Al + gA + (size_t)64 * K);
            pbh0 = *(const uint4*)(Bh + gB); pbh1 = *(const uint4*)(Bh + gB + (size_t)64 * K);
            pbl0 = *(const uint4*)(Bl + gB); pbl1 = *(const uint4*)(Bl + gB + (size_t)64 * K);
        }
#pragma unroll
        for (int ks = 0; ks < 32; ks += 16) {
            unsigned ah[4][4], bhf[4][2], blf[4][2];
#pragma unroll
            for (int i = 0; i < 4; i++) {
                unsigned adr = sA_u + ((wm + i * 16 + a_row) * PADK + ks + a_k8) * 2;
                ldm_x4(ah[i][0], ah[i][1], ah[i][2], ah[i][3], adr);
            }
#pragma unroll
            for (int j2 = 0; j2 < 2; j2++) {
                unsigned adr = sB_u + ((wn + j2 * 16 + b_n) * PADK + ks + b_k8) * 2;
                ldm_x4(bhf[2 * j2][0], bhf[2 * j2][1], bhf[2 * j2 + 1][0], bhf[2 * j2 + 1][1], adr);
                unsigned adrl = sBl_u + ((wn + j2 * 16 + b_n) * PADK + ks + b_k8) * 2;
                ldm_x4(blf[2 * j2][0], blf[2 * j2][1], blf[2 * j2 + 1][0], blf[2 * j2 + 1][1], adrl);
            }
#pragma unroll
            for (int i = 0; i < 4; i++)
#pragma unroll
                for (int j = 0; j < 4; j++) mma16816(acc[i][j], ah[i], bhf[j]);
#pragma unroll
            for (int i = 0; i < 4; i++)
#pragma unroll
                for (int j = 0; j < 4; j++) mma16816(acc[i][j], ah[i], blf[j]);
#pragma unroll
            for (int i = 0; i < 4; i++) {
                unsigned adr = sAl_u + ((wm + i * 16 + a_row) * PADK + ks + a_k8) * 2;
                ldm_x4(ah[i][0], ah[i][1], ah[i][2], ah[i][3], adr);
            }
#pragma unroll
            for (int i = 0; i < 4; i++)
#pragma unroll
                for (int j = 0; j < 4; j++) mma16816(acc[i][j], ah[i], bhf[j]);
        }
        __syncthreads();
        if (t + 1 < nt) {
            *(uint4*)((char*)sAh + soff0) = pah0; *(uint4*)((char*)sAh + soff1) = pah1;
            *(uint4*)((char*)sAl + soff0) = pal0; *(uint4*)((char*)sAl + soff1) = pal1;
            *(uint4*)((char*)sBh + soff0) = pbh0; *(uint4*)((char*)sBh + soff1) = pbh1;
            *(uint4*)((char*)sBl + soff0) = pbl0; *(uint4*)((char*)sBl + soff1) = pbl1;
        }
        __syncthreads();
    }

    // epilogue
    const int grp = lane >> 2, tig = lane & 3;
#pragma unroll
    for (int i = 0; i < 4; i++) {
#pragma unroll
        for (int j = 0; j < 4; j++) {
            int row0 = bm + wm + i * 16 + grp;
            int col = bn + wn + j * 8 + 2 * tig;
            float v0 = acc[i][j][0], v1 = acc[i][j][1];
            float v2 = acc[i][j][2], v3 = acc[i][j][3];
            if (BIAS) {
                float b0 = bias[col], b1 = bias[col + 1];
                v0 += b0; v1 += b1; v2 += b0; v3 += b1;
            }
            if (ACT == 1) {
                v0 = fmaxf(v0, 0.f); v1 = fmaxf(v1, 0.f);
                v2 = fmaxf(v2, 0.f); v3 = fmaxf(v3, 0.f);
            }
            *(float2*)(C + (size_t)row0 * ldc + col) = make_float2(v0, v1);
            *(float2*)(C + (size_t)(row0 + 8) * ldc + col) = make_float2(v2, v3);
        }
    }
}

// ---------------- RMSNorm ---------------------------------------------------
__global__ void rmsnorm_kernel(const float* __restrict__ inp,
                               const float* __restrict__ gamma) {
    int row = blockIdx.x;
    const float* r = inp + (size_t)row * DIM_;
    float s = 0.f;
    for (int j = threadIdx.x; j < DIM_; j += blockDim.x) { float v = r[j]; s += v * v; }
    __shared__ float sh[32];
    for (int o = 16; o; o >>= 1) s += __shfl_down_sync(0xffffffffu, s, o);
    if ((threadIdx.x & 31) == 0) sh[threadIdx.x >> 5] = s;
    __syncthreads();
    if (threadIdx.x < 32) {
        s = (threadIdx.x < (blockDim.x >> 5)) ? sh[threadIdx.x] : 0.f;
        for (int o = 16; o; o >>= 1) s += __shfl_down_sync(0xffffffffu, s, o);
        if (threadIdx.x == 0) sh[0] = rsqrtf(s / (float)DIM_ + 1.1920929e-07f);
    }
    __syncthreads();
    float rs = sh[0];
    for (int j = threadIdx.x; j < DIM_; j += blockDim.x)
        g_x[(size_t)row * DIM_ + j] = r[j] * rs * gamma[j];
}

// ---------------- SGEMM (generalized, 64x64; narrow/odd shapes) --------------
template <int ACT, bool BIAS>
__global__ void sgemm_kernel(const float* __restrict__ A, int lda, long sA,
                             const float* __restrict__ B, int ldb, long sB,
                             const float* __restrict__ bias,
                             float* __restrict__ C, int ldc, long sC,
                             int M, int Ncols, int K) {
    __shared__ float As[16][68];
    __shared__ float Bs[16][64];
    A += (size_t)blockIdx.z * sA;
    B += (size_t)blockIdx.z * sB;
    C += (size_t)blockIdx.z * sC;
    const int bm = blockIdx.y * 64, bn = blockIdx.x * 64;
    const int tid = threadIdx.x;
    const int tx = tid & 15, ty = tid >> 4;
    const int arow = tid >> 2, acol4 = (tid & 3) << 2;
    const int brow = tid >> 4, bcol4 = (tid & 15) << 2;
    float acc[4][4] = {};
    for (int k0 = 0; k0 < K; k0 += 16) {
        float4 av = make_float4(0.f, 0.f, 0.f, 0.f);
        if (bm + arow < M)
            av = *(const float4*)(A + (size_t)(bm + arow) * lda + k0 + acol4);
        As[acol4 + 0][arow] = av.x; As[acol4 + 1][arow] = av.y;
        As[acol4 + 2][arow] = av.z; As[acol4 + 3][arow] = av.w;
        float4 bv = make_float4(0.f, 0.f, 0.f, 0.f);
        if (bn + bcol4 < Ncols)
            bv = *(const float4*)(B + (size_t)(k0 + brow) * ldb + bn + bcol4);
        *(float4*)&Bs[brow][bcol4] = bv;
        __syncthreads();
#pragma unroll
        for (int k = 0; k < 16; k++) {
            float a[4], b[4];
#pragma unroll
            for (int i = 0; i < 4; i++) a[i] = As[k][ty * 4 + i];
#pragma unroll
            for (int j = 0; j < 4; j++) b[j] = Bs[k][tx * 4 + j];
#pragma unroll
            for (int i = 0; i < 4; i++)
#pragma unroll
                for (int j = 0; j < 4; j++) acc[i][j] += a[i] * b[j];
        }
        __syncthreads();
    }
#pragma unroll
    for (int i = 0; i < 4; i++) {
        int rr = bm + ty * 4 + i;
        if (rr >= M) continue;
#pragma unroll
        for (int j = 0; j < 4; j++) {
            int c = bn + tx * 4 + j;
            if (c >= Ncols) continue;
            float v = acc[i][j];
            if (BIAS) v += bias[c];
            if (ACT == 1) v = fmaxf(v, 0.f);
            C[(size_t)rr * ldc + c] = v;
        }
    }
}

// ---------------- split-K reduce (Z=4) ---------------------------------------
template <int ACT>
__global__ void reduce4_kernel(const float* __restrict__ part,
                               const float* __restrict__ bias,
                               float* __restrict__ out, int total, int ncols) {
    int idx = blockIdx.x * blockDim.x + threadIdx.x;
    if (idx >= total) return;
    float v = part[idx] + part[idx + total] + part[idx + 2 * total] +
              part[idx + 3 * total] + bias[idx % ncols];
    if (ACT == 2) v = 1.f / (1.f + expf(-v));
    out[idx] = v;
}

// ---------------- build compression windows ---------------------------------
__global__ void build_windows_kernel(const float* __restrict__ k_pos,
                                     const float* __restrict__ v_pos) {
    int idx = blockIdx.x * blockDim.x + threadIdx.x;
    if (idx >= KVH_ * NCB_ * CBS_ * D_) return;
    int d  = idx % D_;
    int t  = (idx / D_) % CBS_;
    int c  = (idx / (D_ * CBS_)) % NCB_;
    int kh = idx / (D_ * CBS_ * NCB_);
    int pos = c * STRIDE_ + t - (CBS_ - STRIDE_);
    float kv = 0.f, vv = 0.f;
    if (pos >= 0) {
        kv = g_qkv[(size_t)pos * QKVW_ + H_ * D_ + kh * D_ + d];
        vv = g_qkv[(size_t)pos * QKVW_ + (H_ + KVH_) * D_ + kh * D_ + d];
    }
    kv += k_pos[(kh * CBS_ + t) * D_ + d];
    vv += v_pos[(kh * CBS_ + t) * D_ + d];
    size_t row = (size_t)kh * NCB_ + c;
    g_kwflat[row * HID_ + t * D_ + d] = kv;
    g_vwflat[row * HID_ + t * D_ + d] = vv;
}

// ---------------- assemble ckT / cvpad ---------------------------------------
__global__ void assemble_c_kernel(const float* __restrict__ mem_kv) {
    int idx = blockIdx.x * blockDim.x + threadIdx.x;
    if (idx >= KVH_ * CJP_ * D_) return;
    int d  = idx % D_;
    int j  = (idx / D_) % CJP_;
    int kh = idx / (D_ * CJP_);
    float kvv = 0.f, vvv = 0.f;
    if (j < NMEM_) {
        kvv = mem_kv[((0 * KVH_ + kh) * NMEM_ + j) * D_ + d];
        vvv = mem_kv[((1 * KVH_ + kh) * NMEM_ + j) * D_ + d];
    } else if (j < CJ_) {
        kvv = g_ckraw[((size_t)kh * NCB_ + (j - NMEM_)) * D_ + d];
        vvv = g_cvraw[((size_t)kh * NCB_ + (j - NMEM_)) * D_ + d];
    }
    g_ckT[((size_t)kh * D_ + d) * CJP_ + j] = kvv;
    g_cvpad[((size_t)kh * CJP_ + j) * D_ + d] = vvv;
}

// ---------------- RoPE (+ extract non-rope q) --------------------------------
__global__ void rope_kernel() {
    int idx = blockIdx.x * blockDim.x + threadIdx.x;
    if (idx >= (H_ + KVH_) * N_ * (D_ / 2)) return;
    int m = idx % (D_ / 2);
    int n = (idx / (D_ / 2)) % N_;
    int h = idx / ((D_ / 2) * N_);
    float inv = exp2f(-(float)m * (2.0f / (float)D_) * 13.2877123795f);
    float ang = (float)n * inv;
    float c = cosf(ang), s = sinf(ang);
    const float* src;
    float* dst;
    if (h < H_) {
        src = g_qkv + (size_t)n * QKVW_ + h * D_;
        dst = g_rq + ((size_t)h * N_ + n) * D_;
    } else {
        int kh = h - H_;
        src = g_qkv + (size_t)n * QKVW_ + H_ * D_ + kh * D_;
        dst = g_rk + ((size_t)kh * N_ + n) * D_;
    }
    float a = src[2 * m], b = src[2 * m + 1];
    dst[2 * m]     = a * c - b * s;
    dst[2 * m + 1] = b * c + a * s;
    if (h < H_) {
        float* qd = g_qc + ((size_t)h * N_ + n) * D_;
        qd[2 * m] = a; qd[2 * m + 1] = b;
    }
}

// ---------------- importance ---------------------------------------------------
__global__ void importance_kernel() {
    int idx = blockIdx.x * blockDim.x + threadIdx.x;
    if (idx >= KVH_ * N_ * NFB_) return;
    int fb = idx % NFB_;
    int i  = (idx / NFB_) % N_;
    int kh = idx / (NFB_ * N_);
    const float* base = g_csim + (size_t)kh * (GQ_ * N_) * CJP_;
    int c = NMEM_ + 2 * fb;
    float v = base[(size_t)i * CJP_ + c] + base[(size_t)i * CJP_ + c + 1] +
              base[(size_t)(N_ + i) * CJP_ + c] + base[(size_t)(N_ + i) * CJP_ + c + 1];
    g_imp[((size_t)kh * N_ + i) * NFB_ + fb] = 0.25f * SCALE_ * v;
}

// ---------------- compressed softmax -----------------------------------------
__global__ void csoftmax_kernel() {
    int row  = blockIdx.x * 8 + (threadIdx.x >> 5);
    int lane = threadIdx.x & 31;
    float* p = g_csim + (size_t)row * CJP_;
    float v0 = p[lane] * SCALE_, v1 = p[lane + 32] * SCALE_;
    float v2 = p[lane + 64] * SCALE_, v3 = p[lane + 96] * SCALE_;
    float v4 = (lane == 0) ? p[128] * SCALE_ : -FLT_MAX;
    float m = fmaxf(fmaxf(fmaxf(v0, v1), fmaxf(v2, v3)), v4);
    for (int o = 16; o; o >>= 1) m = fmaxf(m, __shfl_xor_sync(0xffffffffu, m, o));
    float e0 = expf(v0 - m), e1 = expf(v1 - m), e2 = expf(v2 - m), e3 = expf(v3 - m);
    float e4 = (lane == 0) ? expf(v4 - m) : 0.f;
    float s = e0 + e1 + e2 + e3 + e4;
    for (int o = 16; o; o >>= 1) s += __shfl_xor_sync(0xffffffffu, s, o);
    float inv = 1.f / s;
    p[lane] = e0 * inv; p[lane + 32] = e1 * inv;
    p[lane + 64] = e2 * inv; p[lane + 96] = e3 * inv;
    if (lane == 0) p[128] = e4 * inv;
    if (lane >= 1 && lane < 16) p[128 + lane] = 0.f;
}

// ---------------- top-k --------------------------------------------------------
__global__ void topk_kernel() {
    int row  = blockIdx.x * 8 + (threadIdx.x >> 5);
    int lane = threadIdx.x & 31;
    int i = row & (N_ - 1);
    int qb = i >> 5;
    const float* ip = g_imp + (size_t)row * NFB_;
    float v0 = (lane == qb)      ? -FLT_MAX : ip[lane];
    float v1 = (lane + 32 == qb) ? -FLT_MAX : ip[lane + 32];
    float m = fmaxf(fmaxf(v0, v1), -1000.f);
    for (int o = 16; o; o >>= 1) m = fmaxf(m, __shfl_xor_sync(0xffffffffu, m, o));
    float s = expf(v0 - m) + expf(v1 - m);
    for (int o = 16; o; o >>= 1) s += __shfl_xor_sync(0xffffffffu, s, o);
    s += expf(-1000.f - m);
    float inv = 1.f / s;
    float p0 = expf(v0 - m) * inv, p1 = expf(v1 - m) * inv;
#pragma unroll
    for (int sel = 0; sel < NSEL_; sel++) {
        float bv; int bi;
        if (p0 >= p1) { bv = p0; bi = lane; } else { bv = p1; bi = lane + 32; }
        for (int o = 16; o; o >>= 1) {
            float ov = __shfl_xor_sync(0xffffffffu, bv, o);
            int   oi = __shfl_xor_sync(0xffffffffu, bi, o);
            if (ov > bv || (ov == bv && oi < bi)) { bv = ov; bi = oi; }
        }
        if (lane == 0) {
            g_selidx[(size_t)row * 5 + sel] = bi;
            g_selflag[(size_t)row * 4 + sel] = (bv > 1e-10f) ? 1 : 0;
        }
        if (bi == lane) p0 = -1.f;
        if (bi == lane + 32) p1 = -1.f;
    }
    if (lane == 0) g_selidx[(size_t)row * 5 + 4] = qb;
}

// ---------------- fine attention ----------------------------------------------
__global__ void fattn_kernel() {
    int i  = blockIdx.x & (N_ - 1);
    int kh = blockIdx.x >> 11;
    __shared__ float qs[2][D_];
    __shared__ float sims[2][5 * SEL_BLK_];
    __shared__ int   sblk[5];
    __shared__ int   sfl[5];
    __shared__ float red[2][2];
    int tid = threadIdx.x;
    int w = tid >> 5, lane = tid & 31;
    if (tid < 5) {
        sblk[tid] = g_selidx[((size_t)kh * N_ + i) * 5 + tid];
        sfl[tid]  = (tid < 4) ? g_selflag[((size_t)kh * N_ + i) * 4 + tid] : 1;
    }
    if (tid < 128) {
        int g = tid >> 6, d = tid & 63;
        qs[g][d] = g_rq[(((size_t)(kh * GQ_ + g)) * N_ + i) * D_ + d];
    }
    __syncthreads();
    {
        float q0a = qs[0][lane], q0b = qs[0][lane + 32];
        float q1a = qs[1][lane], q1b = qs[1][lane + 32];
        int blk = sblk[w];
        bool grpvalid = (w < 4) ? (sfl[w] != 0) : true;
        int lim = (w == 4) ? (i & 31) : 31;
        const float* kbase = g_rk + ((size_t)kh * N_ + blk * SEL_BLK_) * D_;
        for (int kk = 0; kk < SEL_BLK_; kk++) {
            float s0 = -FLT_MAX / 10.f, s1 = -FLT_MAX / 10.f;
            if (grpvalid && kk <= lim) {
                float ka = kbase[kk * D_ + lane], kb = kbase[kk * D_ + lane + 32];
                float p0 = q0a * ka + q0b * kb;
                float p1 = q1a * ka + q1b * kb;
                for (int o = 16; o; o >>= 1) {
                    p0 += __shfl_xor_sync(0xffffffffu, p0, o);
                    p1 += __shfl_xor_sync(0xffffffffu, p1, o);
                }
                s0 = p0 * SCALE_; s1 = p1 * SCALE_;
            }
            if (lane == 0) { sims[0][w * 32 + kk] = s0; sims[1][w * 32 + kk] = s1; }
        }
    }
    __syncthreads();
    if (tid < 64) {
        int g = tid >> 5, l = tid & 31;
        float m = -FLT_MAX;
        for (int j = l; j < 160; j += 32) m = fmaxf(m, sims[g][j]);
        for (int o = 16; o; o >>= 1) m = fmaxf(m, __shfl_xor_sync(0xffffffffu, m, o));
        float sm = 0.f;
        for (int j = l; j < 160; j += 32) sm += expf(sims[g][j] - m);
        for (int o = 16; o; o >>= 1) sm += __shfl_xor_sync(0xffffffffu, sm, o);
        if (l == 0) { red[g][0] = m; red[g][1] = sm; }
    }
    __syncthreads();
    for (int j = tid; j < 320; j += 160) {
        int g = j / 160, jj = j % 160;
        sims[g][jj] = expf(sims[g][jj] - red[g][0]) / red[g][1];
    }
    __syncthreads();
    if (tid < 128) {
        int g = tid >> 6, d = tid & 63;
        const float* vbase = g_qkv + (size_t)(H_ + KVH_) * D_ + kh * D_ + d;
        float acc = 0.f;
#pragma unroll
        for (int s = 0; s < 5; s++) {
            int pb = sblk[s] * SEL_BLK_;
#pragma unroll 8
            for (int t = 0; t < SEL_BLK_; t++)
                acc += sims[g][s * 32 + t] * vbase[(size_t)(pb + t) * QKVW_];
        }
        g_fout[(((size_t)(kh * GQ_ + g)) * N_ + i) * D_ + d] = acc;
    }
}

// ---------------- sliding-window attention ------------------------------------
__global__ void sattn_kernel() {
    extern __shared__ float sm[];
    float* Ks = sm;
    float* Qs = sm + 128 * 65;
    float* Ps = Qs + 64 * 65;
    int tIdx = blockIdx.x, h = blockIdx.y, kh = h >> 1;
    int i0 = tIdx * 64;
    int tid = threadIdx.x, w = tid >> 5, lane = tid & 31;
    for (int idx = tid; idx < 64 * 64; idx += 256) {
        int r = idx >> 6, d = idx & 63;
        Qs[r * 65 + d] = g_rq[((size_t)h * N_ + i0 + r) * D_ + d];
    }
    for (int idx = tid; idx < 128 * 64; idx += 256) {
        int j = idx >> 6, d = idx & 63;
        int p = i0 - 64 + j;
        Ks[j * 65 + d] = (p >= 0) ? g_rk[((size_t)kh * N_ + p) * D_ + d] : 0.f;
    }
    __syncthreads();
#pragma unroll
    for (int rr = 0; rr < 8; rr++) {
        int r = w * 8 + rr;
        int j0 = lane, j1 = lane + 32, j2 = lane + 64, j3 = lane + 96;
        float a0 = 0.f, a1 = 0.f, a2 = 0.f, a3 = 0.f;
        for (int d = 0; d < 64; d++) {
            float q = Qs[r * 65 + d];
            a0 += q * Ks[j0 * 65 + d]; a1 += q * Ks[j1 * 65 + d];
            a2 += q * Ks[j2 * 65 + d]; a3 += q * Ks[j3 * 65 + d];
        }
        float s0, s1, s2, s3;
        {
            bool ok;
            ok = (j0 >= r + 1) && (j0 <= r + 64) && (i0 - 64 + j0 >= 0);
            s0 = ok ? a0 * SCALE_ : -FLT_MAX;
            ok = (j1 >= r + 1) && (j1 <= r + 64) && (i0 - 64 + j1 >= 0);
            s1 = ok ? a1 * SCALE_ : -FLT_MAX;
            ok = (j2 >= r + 1) && (j2 <= r + 64) && (i0 - 64 + j2 >= 0);
            s2 = ok ? a2 * SCALE_ : -FLT_MAX;
            ok = (j3 >= r + 1) && (j3 <= r + 64) && (i0 - 64 + j3 >= 0);
            s3 = ok ? a3 * SCALE_ : -FLT_MAX;
        }
        float m = fmaxf(fmaxf(s0, s1), fmaxf(s2, s3));
        for (int o = 16; o; o >>= 1) m = fmaxf(m, __shfl_xor_sync(0xffffffffu, m, o));
        float e0 = expf(s0 - m), e1 = expf(s1 - m), e2 = expf(s2 - m), e3 = expf(s3 - m);
        float su = e0 + e1 + e2 + e3;
        for (int o = 16; o; o >>= 1) su += __shfl_xor_sync(0xffffffffu, su, o);
        float inv = 1.f / su;
        Ps[r * 128 + j0] = e0 * inv; Ps[r * 128 + j1] = e1 * inv;
        Ps[r * 128 + j2] = e2 * inv; Ps[r * 128 + j3] = e3 * inv;
    }
    __syncthreads();
    for (int idx = tid; idx < 128 * 64; idx += 256) {
        int j = idx >> 6, d = idx & 63;
        int p = i0 - 64 + j;
        Ks[j * 65 + d] = (p >= 0)
            ? g_qkv[(size_t)p * QKVW_ + (H_ + KVH_) * D_ + kh * D_ + d] : 0.f;
    }
    __syncthreads();
#pragma unroll
    for (int rr = 0; rr < 8; rr++) {
        int r = w * 8 + rr;
        float a0 = 0.f, a1 = 0.f;
        for (int j = 0; j < 128; j++) {
            float p = Ps[r * 128 + j];
            a0 += p * Ks[j * 65 + lane];
            a1 += p * Ks[j * 65 + lane + 32];
        }
        size_t ob = ((size_t)h * N_ + i0 + r) * D_;
        g_sout[ob + lane] = a0;
        g_sout[ob + lane + 32] = a1;
    }
}

// ---------------- gated combine ------------------------------------------------
__global__ void combine_kernel() {
    int idx = blockIdx.x * blockDim.x + threadIdx.x;
    if (idx >= N_ * H_ * D_) return;
    int d = idx % D_;
    int h = (idx / D_) % H_;
    int n = idx / (D_ * H_);
    const float* g = g_gates + ((size_t)n * H_ + h) * 3;
    size_t hnd = ((size_t)h * N_ + n) * D_ + d;
    g_comb[(size_t)n * DIM_ + h * D_ + d] =
        g[0] * g_cout[hnd] + g[1] * g_fout[hnd] + g[2] * g_sout[hnd];
}

// ---------------- launch -------------------------------------------------------
extern "C" void kernel_launch(void* const* d_in, const int* in_sizes, int n_in,
                              void* d_out, int out_size) {
    const float* inp    = (const float*)d_in[0];
    const float* norm_g = (const float*)d_in[1];
    const float* Wqkv   = (const float*)d_in[2];
    const float* mem_kv = (const float*)d_in[3];
    const float* k_pos  = (const float*)d_in[4];
    const float* v_pos  = (const float*)d_in[5];
    const float* kW1    = (const float*)d_in[6];
    const float* kb1    = (const float*)d_in[7];
    const float* kW2    = (const float*)d_in[8];
    const float* kb2    = (const float*)d_in[9];
    const float* vW1    = (const float*)d_in[10];
    const float* vb1    = (const float*)d_in[11];
    const float* vW2    = (const float*)d_in[12];
    const float* vb2    = (const float*)d_in[13];
    const float* combW  = (const float*)d_in[14];
    const float* combB  = (const float*)d_in[15];
    const float* Wout   = (const float*)d_in[16];
    float* out = (float*)d_out;

    float* px;     cudaGetSymbolAddress((void**)&px, g_x);
    float* pqkv;   cudaGetSymbolAddress((void**)&pqkv, g_qkv);
    float* pkw;    cudaGetSymbolAddress((void**)&pkw, g_kwflat);
    float* pvw;    cudaGetSymbolAddress((void**)&pvw, g_vwflat);
    float* ph1;    cudaGetSymbolAddress((void**)&ph1, g_h1);
    float* pckr;   cudaGetSymbolAddress((void**)&pckr, g_ckraw);
    float* pcvr;   cudaGetSymbolAddress((void**)&pcvr, g_cvraw);
    float* pckT;   cudaGetSymbolAddress((void**)&pckT, g_ckT);
    float* pcvp;   cudaGetSymbolAddress((void**)&pcvp, g_cvpad);
    float* pqc;    cudaGetSymbolAddress((void**)&pqc, g_qc);
    float* pcsim;  cudaGetSymbolAddress((void**)&pcsim, g_csim);
    float* pcout;  cudaGetSymbolAddress((void**)&pcout, g_cout);
    float* ppart;  cudaGetSymbolAddress((void**)&ppart, g_part);
    float* pgates; cudaGetSymbolAddress((void**)&pgates, g_gates);
    float* pcomb;  cudaGetSymbolAddress((void**)&pcomb, g_comb);
    __nv_bfloat16 *pah, *pal, *pbh, *pbl;
    cudaGetSymbolAddress((void**)&pah, g_ah);
    cudaGetSymbolAddress((void**)&pal, g_al);
    cudaGetSymbolAddress((void**)&pbh, g_bh);
    cudaGetSymbolAddress((void**)&pbl, g_bl);

    const int SATTN_SMEM = (128 * 65 + 64 * 65 + 64 * 128) * 4;
    cudaFuncSetAttribute(sattn_kernel, cudaFuncAttributeMaxDynamicSharedMemorySize, SATTN_SMEM);

    // 1. RMSNorm
    rmsnorm_kernel<<<N_, 256>>>(inp, norm_g);
    // 2. qkv = x @ Wqkv  (HMMA bf16 split)
    transpose_split_kernel<<<dim3(QKVW_ / 32, DIM_ / 32), dim3(32, 8)>>>(Wqkv, DIM_, QKVW_, pbh, pbl);
    split_kernel<<<(N_ * DIM_ + 255) / 256, 256>>>(px, N_ * DIM_, pah, pal);
    tcgemm_kernel<0, false><<<dim3(QKVW_ / 128, N_ / 128), 256>>>(
        pah, pal, pbh, pbl, nullptr, pqkv, QKVW_, N_, QKVW_, DIM_);
    // 3. windows + rope/qc
    build_windows_kernel<<<(KVH_ * NCB_ * CBS_ * D_ + 255) / 256, 256>>>(k_pos, v_pos);
    rope_kernel<<<((H_ + KVH_) * N_ * (D_ / 2) + 255) / 256, 256>>>();
    // 4a. k-compression MLP layer 1 (HMMA)
    transpose_split_kernel<<<dim3(HID_ / 32, HID_ / 32), dim3(32, 8)>>>(kW1, HID_, HID_, pbh, pbl);
    split_kernel<<<(KVH_ * NCB_ * HID_ + 255) / 256, 256>>>(pkw, KVH_ * NCB_ * HID_, pah, pal);
    tcgemm_kernel<1, true><<<dim3(HID_ / 128, (KVH_ * NCB_) / 128), 256>>>(
        pah, pal, pbh, pbl, kb1, ph1, HID_, KVH_ * NCB_, HID_, HID_);
    sgemm_kernel<0, false><<<dim3(1, 16, 4), 256>>>(ph1, HID_, 512, kW2, D_, (long)512 * D_,
                                                    nullptr, ppart, D_, (long)1024 * D_,
                                                    KVH_ * NCB_, D_, 512);
    reduce4_kernel<0><<<(1024 * D_ + 255) / 256, 256>>>(ppart, kb2, pckr, 1024 * D_, D_);
    // 4b. v-compression MLP layer 1 (HMMA)
    transpose_split_kernel<<<dim3(HID_ / 32, HID_ / 32), dim3(32, 8)>>>(vW1, HID_, HID_, pbh, pbl);
    split_kernel<<<(KVH_ * NCB_ * HID_ + 255) / 256, 256>>>(pvw, KVH_ * NCB_ * HID_, pah, pal);
    tcgemm_kernel<1, true><<<dim3(HID_ / 128, (KVH_ * NCB_) / 128), 256>>>(
        pah, pal, pbh, pbl, vb1, ph1, HID_, KVH_ * NCB_, HID_, HID_);
    sgemm_kernel<0, false><<<dim3(1, 16, 4), 256>>>(ph1, HID_, 512, vW2, D_, (long)512 * D_,
                                                    nullptr, ppart, D_, (long)1024 * D_,
                                                    KVH_ * NCB_, D_, 512);
    reduce4_kernel<0><<<(1024 * D_ + 255) / 256, 256>>>(ppart, vb2, pcvr, 1024 * D_, D_);
    // 5. assemble ckT / cvpad
    assemble_c_kernel<<<(KVH_ * CJP_ * D_ + 255) / 256, 256>>>(mem_kv);
    // 6. compressed attention (batched fp32 GEMMs + softmax)
    sgemm_kernel<0, false><<<dim3(3, 64, KVH_), 256>>>(
        pqc, D_, (long)(GQ_ * N_) * D_, pckT, CJP_, (long)D_ * CJP_, nullptr,
        pcsim, CJP_, (long)(GQ_ * N_) * CJP_, GQ_ * N_, CJ_, D_);
    importance_kernel<<<(KVH_ * N_ * NFB_ + 255) / 256, 256>>>();
    csoftmax_kernel<<<KVH_ * GQ_ * N_ / 8, 256>>>();
    sgemm_kernel<0, false><<<dim3(1, 64, KVH_), 256>>>(
        pcsim, CJP_, (long)(GQ_ * N_) * CJP_, pcvp, D_, (long)CJP_ * D_, nullptr,
        pcout, D_, (long)(GQ_ * N_) * D_, GQ_ * N_, D_, CJP_);
    // 7. top-k + fine attention
    topk_kernel<<<KVH_ * N_ / 8, 256>>>();
    fattn_kernel<<<KVH_ * N_, 160>>>();
    // 8. sliding-window attention
    sattn_kernel<<<dim3(N_ / 64, H_), 256, SATTN_SMEM>>>();
    // 9. gates + combine
    sgemm_kernel<0, false><<<dim3(1, 32, 4), 256>>>(px, DIM_, 256, combW, 48, (long)256 * 48,
                                                    nullptr, ppart, 48, (long)N_ * 48,
                                                    N_, 48, 256);
    reduce4_kernel<2><<<(N_ * 48 + 255) / 256, 256>>>(ppart, combB, pgates, N_ * 48, 48);
    combine_kernel<<<(N_ * H_ * D_ + 255) / 256, 256>>>();
    // 10. out = comb @ Wout (HMMA)
    transpose_split_kernel<<<dim3(DIM_ / 32, DIM_ / 32), dim3(32, 8)>>>(Wout, DIM_, DIM_, pbh, pbl);
    split_kernel<<<(N_ * DIM_ + 255) / 256, 256>>>(pcomb, N_ * DIM_, pah, pal);
    tcgemm_kernel<0, false><<<dim3(DIM_ / 128, N_ / 128), 256>>>(
        pah, pal, pbh, pbl, nullptr, out, DIM_, N_, DIM_, DIM_);
}

// round 7
// speedup vs baseline: 2.1637x; 1.0465x over previous
#include <cuda_runtime.h>
#include <cuda_bf16.h>
#include <math.h>
#include <float.h>

#define N_      2048
#define DIM_    1024
#define H_      16
#define KVH_    8
#define GQ_     2
#define D_      64
#define WS_     64
#define CBS_    32
#define STRIDE_ 16
#define SEL_BLK_ 32
#define NSEL_   4
#define NMEM_   1
#define NCB_    128
#define NFB_    64
#define HID_    2048
#define SCALE_  0.125f
#define QKVW_   2048
#define CJ_     (NMEM_ + NCB_)
#define CJP_    144
#define PADK    40              /* 32 data + 8 pad bf16 per smem row */

// ---------------- scratch -----------------------------------------------------
__device__ float g_x[N_ * DIM_];
__device__ float g_qkv[N_ * QKVW_];
__device__ float g_kwflat[KVH_ * NCB_ * HID_];
__device__ float g_vwflat[KVH_ * NCB_ * HID_];
__device__ float g_h1[KVH_ * NCB_ * HID_];
__device__ float g_ckraw[KVH_ * NCB_ * D_];
__device__ float g_cvraw[KVH_ * NCB_ * D_];
__device__ float g_ckT[KVH_ * D_ * CJP_];
__device__ float g_cvpad[KVH_ * CJP_ * D_];
__device__ float g_qc[H_ * N_ * D_];
__device__ float g_csim[KVH_ * (GQ_ * N_) * CJP_];
__device__ float g_rq[H_ * N_ * D_];
__device__ float g_rk[KVH_ * N_ * D_];
__device__ float g_cout[H_ * N_ * D_];
__device__ float g_fout[H_ * N_ * D_];
__device__ float g_sout[H_ * N_ * D_];
__device__ float g_imp[KVH_ * N_ * NFB_];
__device__ int   g_selidx[KVH_ * N_ * 5];
__device__ int   g_selflag[KVH_ * N_ * 4];
__device__ float g_gates[N_ * H_ * 3];
__device__ float g_comb[N_ * DIM_];
__device__ float g_part[8 * N_ * 64];
__device__ __nv_bfloat16 g_ah[2 * 1024 * 1024];
__device__ __nv_bfloat16 g_al[2 * 1024 * 1024];
__device__ __nv_bfloat16 g_bh[4 * 1024 * 1024];
__device__ __nv_bfloat16 g_bl[4 * 1024 * 1024];

// ---------------- warp-MMA helpers (sm_80+ PTX, sm_103-safe) ------------------
__device__ __forceinline__ unsigned smem_u32(const void* p) {
    unsigned a;
    asm("{ .reg .u64 t; cvta.to.shared.u64 t, %1; cvt.u32.u64 %0, t; }"
        : "=r"(a) : "l"(p));
    return a;
}
__device__ __forceinline__ void ldm_x4(unsigned& r0, unsigned& r1,
                                       unsigned& r2, unsigned& r3, unsigned a) {
    asm volatile("ldmatrix.sync.aligned.m8n8.x4.shared.b16 {%0,%1,%2,%3}, [%4];"
                 : "=r"(r0), "=r"(r1), "=r"(r2), "=r"(r3) : "r"(a));
}
__device__ __forceinline__ void mma16816(float* c, const unsigned* a,
                                         const unsigned* b) {
    asm volatile(
        "mma.sync.aligned.m16n8k16.row.col.f32.bf16.bf16.f32 "
        "{%0,%1,%2,%3}, {%4,%5,%6,%7}, {%8,%9}, {%0,%1,%2,%3};"
        : "+f"(c[0]), "+f"(c[1]), "+f"(c[2]), "+f"(c[3])
        : "r"(a[0]), "r"(a[1]), "r"(a[2]), "r"(a[3]), "r"(b[0]), "r"(b[1]));
}

// ---------------- hi/lo split kernels ----------------------------------------
__global__ void split_kernel(const float* __restrict__ in, int total,
                             __nv_bfloat16* __restrict__ oh,
                             __nv_bfloat16* __restrict__ ol) {
    int idx = blockIdx.x * blockDim.x + threadIdx.x;
    if (idx >= total) return;
    float v = in[idx];
    __nv_bfloat16 h = __float2bfloat16(v);
    oh[idx] = h;
    ol[idx] = __float2bfloat16(v - __bfloat162float(h));
}

__global__ void transpose_split_kernel(const float* __restrict__ in, int R, int C,
                                       __nv_bfloat16* __restrict__ oh,
                                       __nv_bfloat16* __restrict__ ol) {
    __shared__ float t[32][33];
    int c0 = blockIdx.x * 32, r0 = blockIdx.y * 32;
    int tx = threadIdx.x, ty = threadIdx.y;
#pragma unroll
    for (int j = 0; j < 32; j += 8)
        t[ty + j][tx] = in[(size_t)(r0 + ty + j) * C + c0 + tx];
    __syncthreads();
#pragma unroll
    for (int j = 0; j < 32; j += 8) {
        float v = t[tx][ty + j];
        __nv_bfloat16 h = __float2bfloat16(v);
        size_t o = (size_t)(c0 + ty + j) * R + r0 + tx;
        oh[o] = h;
        ol[o] = __float2bfloat16(v - __bfloat162float(h));
    }
}

// ---------------- tensor-core GEMM via mma.sync (bf16 split, fp32 acc) -------
// A [M,K] bf16 hi/lo; B [N,K] bf16 hi/lo. C = act(A·B^T + bias)
// CTA 128x128, BK=32, 512 thr / 16 warps (4m x 4n), warp tile 32x32.
template <int ACT, bool BIAS>
__global__ __launch_bounds__(512, 1)
void tcgemm_kernel(const __nv_bfloat16* __restrict__ Ah,
                   const __nv_bfloat16* __restrict__ Al,
                   const __nv_bfloat16* __restrict__ Bh,
                   const __nv_bfloat16* __restrict__ Bl,
                   const float* __restrict__ bias,
                   float* __restrict__ C, int ldc,
                   int M, int Ncols, int K) {
    __shared__ __nv_bfloat16 sAh[128 * PADK];
    __shared__ __nv_bfloat16 sAl[128 * PADK];
    __shared__ __nv_bfloat16 sBh[128 * PADK];
    __shared__ __nv_bfloat16 sBl[128 * PADK];
    const int tid = threadIdx.x;
    const int wid = tid >> 5, lane = tid & 31;
    const int bm = blockIdx.y * 128, bn = blockIdx.x * 128;
    const int wm = (wid & 3) * 32, wn = (wid >> 2) * 32;

    // global->smem: one uint4 per thread per tile
    const int r = tid >> 2, c16 = tid & 3;
    const unsigned sA_u = smem_u32(sAh), sAl_u = smem_u32(sAl);
    const unsigned sB_u = smem_u32(sBh), sBl_u = smem_u32(sBl);
    const unsigned soff = (r * PADK + c16 * 8) * 2;

    float acc[2][4][4];
#pragma unroll
    for (int i = 0; i < 2; i++)
#pragma unroll
        for (int j = 0; j < 4; j++)
#pragma unroll
            for (int c = 0; c < 4; c++) acc[i][j][c] = 0.f;

    const int nt = K >> 5;
    uint4 pah, pal, pbh, pbl;
    {
        size_t gA = (size_t)(bm + r) * K + c16 * 8;
        size_t gB = (size_t)(bn + r) * K + c16 * 8;
        pah = *(const uint4*)(Ah + gA);
        pal = *(const uint4*)(Al + gA);
        pbh = *(const uint4*)(Bh + gB);
        pbl = *(const uint4*)(Bl + gB);
    }
    *(uint4*)((char*)sAh + soff) = pah;
    *(uint4*)((char*)sAl + soff) = pal;
    *(uint4*)((char*)sBh + soff) = pbh;
    *(uint4*)((char*)sBl + soff) = pbl;
    __syncthreads();

    const int a_row = (lane & 15), a_k8 = (lane >> 4) << 3;
    const int b_n = (lane & 7) + ((lane >> 4) << 3), b_k8 = (lane & 8);

    for (int t = 0; t < nt; t++) {
        if (t + 1 < nt) {
            size_t gA = (size_t)(bm + r) * K + (t + 1) * 32 + c16 * 8;
            size_t gB = (size_t)(bn + r) * K + (t + 1) * 32 + c16 * 8;
            pah = *(const uint4*)(Ah + gA);
            pal = *(const uint4*)(Al + gA);
            pbh = *(const uint4*)(Bh + gB);
            pbl = *(const uint4*)(Bl + gB);
        }
#pragma unroll
        for (int ks = 0; ks < 32; ks += 16) {
            unsigned ah[2][4], al[2][4], bhf[4][2], blf[4][2];
#pragma unroll
            for (int i = 0; i < 2; i++) {
                unsigned adr = sA_u + ((wm + i * 16 + a_row) * PADK + ks + a_k8) * 2;
                ldm_x4(ah[i][0], ah[i][1], ah[i][2], ah[i][3], adr);
                unsigned adrl = sAl_u + ((wm + i * 16 + a_row) * PADK + ks + a_k8) * 2;
                ldm_x4(al[i][0], al[i][1], al[i][2], al[i][3], adrl);
            }
#pragma unroll
            for (int j2 = 0; j2 < 2; j2++) {
                unsigned adr = sB_u + ((wn + j2 * 16 + b_n) * PADK + ks + b_k8) * 2;
                ldm_x4(bhf[2 * j2][0], bhf[2 * j2][1], bhf[2 * j2 + 1][0], bhf[2 * j2 + 1][1], adr);
                unsigned adrl = sBl_u + ((wn + j2 * 16 + b_n) * PADK + ks + b_k8) * 2;
                ldm_x4(blf[2 * j2][0], blf[2 * j2][1], blf[2 * j2 + 1][0], blf[2 * j2 + 1][1], adrl);
            }
#pragma unroll
            for (int i = 0; i < 2; i++)
#pragma unroll
                for (int j = 0; j < 4; j++) {
                    mma16816(acc[i][j], ah[i], bhf[j]);
                    mma16816(acc[i][j], ah[i], blf[j]);
                    mma16816(acc[i][j], al[i], bhf[j]);
                }
        }
        __syncthreads();
        if (t + 1 < nt) {
            *(uint4*)((char*)sAh + soff) = pah;
            *(uint4*)((char*)sAl + soff) = pal;
            *(uint4*)((char*)sBh + soff) = pbh;
            *(uint4*)((char*)sBl + soff) = pbl;
        }
        __syncthreads();
    }

    const int grp = lane >> 2, tig = lane & 3;
#pragma unroll
    for (int i = 0; i < 2; i++) {
#pragma unroll
        for (int j = 0; j < 4; j++) {
            int row0 = bm + wm + i * 16 + grp;
            int col = bn + wn + j * 8 + 2 * tig;
            float v0 = acc[i][j][0], v1 = acc[i][j][1];
            float v2 = acc[i][j][2], v3 = acc[i][j][3];
            if (BIAS) {
                float b0 = bias[col], b1 = bias[col + 1];
                v0 += b0; v1 += b1; v2 += b0; v3 += b1;
            }
            if (ACT == 1) {
                v0 = fmaxf(v0, 0.f); v1 = fmaxf(v1, 0.f);
                v2 = fmaxf(v2, 0.f); v3 = fmaxf(v3, 0.f);
            }
            *(float2*)(C + (size_t)row0 * ldc + col) = make_float2(v0, v1);
            *(float2*)(C + (size_t)(row0 + 8) * ldc + col) = make_float2(v2, v3);
        }
    }
}

// ---------------- RMSNorm ---------------------------------------------------
__global__ void rmsnorm_kernel(const float* __restrict__ inp,
                               const float* __restrict__ gamma) {
    int row = blockIdx.x;
    const float* r = inp + (size_t)row * DIM_;
    float s = 0.f;
    for (int j = threadIdx.x; j < DIM_; j += blockDim.x) { float v = r[j]; s += v * v; }
    __shared__ float sh[32];
    for (int o = 16; o; o >>= 1) s += __shfl_down_sync(0xffffffffu, s, o);
    if ((threadIdx.x & 31) == 0) sh[threadIdx.x >> 5] = s;
    __syncthreads();
    if (threadIdx.x < 32) {
        s = (threadIdx.x < (blockDim.x >> 5)) ? sh[threadIdx.x] : 0.f;
        for (int o = 16; o; o >>= 1) s += __shfl_down_sync(0xffffffffu, s, o);
        if (threadIdx.x == 0) sh[0] = rsqrtf(s / (float)DIM_ + 1.1920929e-07f);
    }
    __syncthreads();
    float rs = sh[0];
    for (int j = threadIdx.x; j < DIM_; j += blockDim.x)
        g_x[(size_t)row * DIM_ + j] = r[j] * rs * gamma[j];
}

// ---------------- SGEMM (generalized, 64x64; narrow/odd shapes) --------------
template <int ACT, bool BIAS>
__global__ void sgemm_kernel(const float* __restrict__ A, int lda, long sA,
                             const float* __restrict__ B, int ldb, long sB,
                             const float* __restrict__ bias,
                             float* __restrict__ C, int ldc, long sC,
                             int M, int Ncols, int K) {
    __shared__ float As[16][68];
    __shared__ float Bs[16][64];
    A += (size_t)blockIdx.z * sA;
    B += (size_t)blockIdx.z * sB;
    C += (size_t)blockIdx.z * sC;
    const int bm = blockIdx.y * 64, bn = blockIdx.x * 64;
    const int tid = threadIdx.x;
    const int tx = tid & 15, ty = tid >> 4;
    const int arow = tid >> 2, acol4 = (tid & 3) << 2;
    const int brow = tid >> 4, bcol4 = (tid & 15) << 2;
    float acc[4][4] = {};
    for (int k0 = 0; k0 < K; k0 += 16) {
        float4 av = make_float4(0.f, 0.f, 0.f, 0.f);
        if (bm + arow < M)
            av = *(const float4*)(A + (size_t)(bm + arow) * lda + k0 + acol4);
        As[acol4 + 0][arow] = av.x; As[acol4 + 1][arow] = av.y;
        As[acol4 + 2][arow] = av.z; As[acol4 + 3][arow] = av.w;
        float4 bv = make_float4(0.f, 0.f, 0.f, 0.f);
        if (bn + bcol4 < Ncols)
            bv = *(const float4*)(B + (size_t)(k0 + brow) * ldb + bn + bcol4);
        *(float4*)&Bs[brow][bcol4] = bv;
        __syncthreads();
#pragma unroll
        for (int k = 0; k < 16; k++) {
            float a[4], b[4];
#pragma unroll
            for (int i = 0; i < 4; i++) a[i] = As[k][ty * 4 + i];
#pragma unroll
            for (int j = 0; j < 4; j++) b[j] = Bs[k][tx * 4 + j];
#pragma unroll
            for (int i = 0; i < 4; i++)
#pragma unroll
                for (int j = 0; j < 4; j++) acc[i][j] += a[i] * b[j];
        }
        __syncthreads();
    }
#pragma unroll
    for (int i = 0; i < 4; i++) {
        int rr = bm + ty * 4 + i;
        if (rr >= M) continue;
#pragma unroll
        for (int j = 0; j < 4; j++) {
            int c = bn + tx * 4 + j;
            if (c >= Ncols) continue;
            float v = acc[i][j];
            if (BIAS) v += bias[c];
            if (ACT == 1) v = fmaxf(v, 0.f);
            C[(size_t)rr * ldc + c] = v;
        }
    }
}

// ---------------- split-K reduce (Z=8) ---------------------------------------
template <int ACT>
__global__ void reduce8_kernel(const float* __restrict__ part,
                               const float* __restrict__ bias,
                               float* __restrict__ out, int total, int ncols) {
    int idx = blockIdx.x * blockDim.x + threadIdx.x;
    if (idx >= total) return;
    float v = bias[idx % ncols];
#pragma unroll
    for (int k = 0; k < 8; k++) v += part[idx + (size_t)k * total];
    if (ACT == 2) v = 1.f / (1.f + expf(-v));
    out[idx] = v;
}

// ---------------- build compression windows ---------------------------------
__global__ void build_windows_kernel(const float* __restrict__ k_pos,
                                     const float* __restrict__ v_pos) {
    int idx = blockIdx.x * blockDim.x + threadIdx.x;
    if (idx >= KVH_ * NCB_ * CBS_ * D_) return;
    int d  = idx % D_;
    int t  = (idx / D_) % CBS_;
    int c  = (idx / (D_ * CBS_)) % NCB_;
    int kh = idx / (D_ * CBS_ * NCB_);
    int pos = c * STRIDE_ + t - (CBS_ - STRIDE_);
    float kv = 0.f, vv = 0.f;
    if (pos >= 0) {
        kv = g_qkv[(size_t)pos * QKVW_ + H_ * D_ + kh * D_ + d];
        vv = g_qkv[(size_t)pos * QKVW_ + (H_ + KVH_) * D_ + kh * D_ + d];
    }
    kv += k_pos[(kh * CBS_ + t) * D_ + d];
    vv += v_pos[(kh * CBS_ + t) * D_ + d];
    size_t row = (size_t)kh * NCB_ + c;
    g_kwflat[row * HID_ + t * D_ + d] = kv;
    g_vwflat[row * HID_ + t * D_ + d] = vv;
}

// ---------------- assemble ckT / cvpad ---------------------------------------
__global__ void assemble_c_kernel(const float* __restrict__ mem_kv) {
    int idx = blockIdx.x * blockDim.x + threadIdx.x;
    if (idx >= KVH_ * CJP_ * D_) return;
    int d  = idx % D_;
    int j  = (idx / D_) % CJP_;
    int kh = idx / (D_ * CJP_);
    float kvv = 0.f, vvv = 0.f;
    if (j < NMEM_) {
        kvv = mem_kv[((0 * KVH_ + kh) * NMEM_ + j) * D_ + d];
        vvv = mem_kv[((1 * KVH_ + kh) * NMEM_ + j) * D_ + d];
    } else if (j < CJ_) {
        kvv = g_ckraw[((size_t)kh * NCB_ + (j - NMEM_)) * D_ + d];
        vvv = g_cvraw[((size_t)kh * NCB_ + (j - NMEM_)) * D_ + d];
    }
    g_ckT[((size_t)kh * D_ + d) * CJP_ + j] = kvv;
    g_cvpad[((size_t)kh * CJP_ + j) * D_ + d] = vvv;
}

// ---------------- RoPE (+ extract non-rope q) --------------------------------
__global__ void rope_kernel() {
    int idx = blockIdx.x * blockDim.x + threadIdx.x;
    if (idx >= (H_ + KVH_) * N_ * (D_ / 2)) return;
    int m = idx % (D_ / 2);
    int n = (idx / (D_ / 2)) % N_;
    int h = idx / ((D_ / 2) * N_);
    float inv = exp2f(-(float)m * (2.0f / (float)D_) * 13.2877123795f);
    float ang = (float)n * inv;
    float c = cosf(ang), s = sinf(ang);
    const float* src;
    float* dst;
    if (h < H_) {
        src = g_qkv + (size_t)n * QKVW_ + h * D_;
        dst = g_rq + ((size_t)h * N_ + n) * D_;
    } else {
        int kh = h - H_;
        src = g_qkv + (size_t)n * QKVW_ + H_ * D_ + kh * D_;
        dst = g_rk + ((size_t)kh * N_ + n) * D_;
    }
    float a = src[2 * m], b = src[2 * m + 1];
    dst[2 * m]     = a * c - b * s;
    dst[2 * m + 1] = b * c + a * s;
    if (h < H_) {
        float* qd = g_qc + ((size_t)h * N_ + n) * D_;
        qd[2 * m] = a; qd[2 * m + 1] = b;
    }
}

// ---------------- importance ---------------------------------------------------
__global__ void importance_kernel() {
    int idx = blockIdx.x * blockDim.x + threadIdx.x;
    if (idx >= KVH_ * N_ * NFB_) return;
    int fb = idx % NFB_;
    int i  = (idx / NFB_) % N_;
    int kh = idx / (NFB_ * N_);
    const float* base = g_csim + (size_t)kh * (GQ_ * N_) * CJP_;
    int c = NMEM_ + 2 * fb;
    float v = base[(size_t)i * CJP_ + c] + base[(size_t)i * CJP_ + c + 1] +
              base[(size_t)(N_ + i) * CJP_ + c] + base[(size_t)(N_ + i) * CJP_ + c + 1];
    g_imp[((size_t)kh * N_ + i) * NFB_ + fb] = 0.25f * SCALE_ * v;
}

// ---------------- compressed softmax -----------------------------------------
__global__ void csoftmax_kernel() {
    int row  = blockIdx.x * 8 + (threadIdx.x >> 5);
    int lane = threadIdx.x & 31;
    float* p = g_csim + (size_t)row * CJP_;
    float v0 = p[lane] * SCALE_, v1 = p[lane + 32] * SCALE_;
    float v2 = p[lane + 64] * SCALE_, v3 = p[lane + 96] * SCALE_;
    float v4 = (lane == 0) ? p[128] * SCALE_ : -FLT_MAX;
    float m = fmaxf(fmaxf(fmaxf(v0, v1), fmaxf(v2, v3)), v4);
    for (int o = 16; o; o >>= 1) m = fmaxf(m, __shfl_xor_sync(0xffffffffu, m, o));
    float e0 = expf(v0 - m), e1 = expf(v1 - m), e2 = expf(v2 - m), e3 = expf(v3 - m);
    float e4 = (lane == 0) ? expf(v4 - m) : 0.f;
    float s = e0 + e1 + e2 + e3 + e4;
    for (int o = 16; o; o >>= 1) s += __shfl_xor_sync(0xffffffffu, s, o);
    float inv = 1.f / s;
    p[lane] = e0 * inv; p[lane + 32] = e1 * inv;
    p[lane + 64] = e2 * inv; p[lane + 96] = e3 * inv;
    if (lane == 0) p[128] = e4 * inv;
    if (lane >= 1 && lane < 16) p[128 + lane] = 0.f;
}

// ---------------- top-k --------------------------------------------------------
__global__ void topk_kernel() {
    int row  = blockIdx.x * 8 + (threadIdx.x >> 5);
    int lane = threadIdx.x & 31;
    int i = row & (N_ - 1);
    int qb = i >> 5;
    const float* ip = g_imp + (size_t)row * NFB_;
    float v0 = (lane == qb)      ? -FLT_MAX : ip[lane];
    float v1 = (lane + 32 == qb) ? -FLT_MAX : ip[lane + 32];
    float m = fmaxf(fmaxf(v0, v1), -1000.f);
    for (int o = 16; o; o >>= 1) m = fmaxf(m, __shfl_xor_sync(0xffffffffu, m, o));
    float s = expf(v0 - m) + expf(v1 - m);
    for (int o = 16; o; o >>= 1) s += __shfl_xor_sync(0xffffffffu, s, o);
    s += expf(-1000.f - m);
    float inv = 1.f / s;
    float p0 = expf(v0 - m) * inv, p1 = expf(v1 - m) * inv;
#pragma unroll
    for (int sel = 0; sel < NSEL_; sel++) {
        float bv; int bi;
        if (p0 >= p1) { bv = p0; bi = lane; } else { bv = p1; bi = lane + 32; }
        for (int o = 16; o; o >>= 1) {
            float ov = __shfl_xor_sync(0xffffffffu, bv, o);
            int   oi = __shfl_xor_sync(0xffffffffu, bi, o);
            if (ov > bv || (ov == bv && oi < bi)) { bv = ov; bi = oi; }
        }
        if (lane == 0) {
            g_selidx[(size_t)row * 5 + sel] = bi;
            g_selflag[(size_t)row * 4 + sel] = (bv > 1e-10f) ? 1 : 0;
        }
        if (bi == lane) p0 = -1.f;
        if (bi == lane + 32) p1 = -1.f;
    }
    if (lane == 0) g_selidx[(size_t)row * 5 + 4] = qb;
}

// ---------------- fine attention (smem-transposed K, lane-per-key QK) ---------
__global__ void fattn_kernel() {
    int i  = blockIdx.x & (N_ - 1);
    int kh = blockIdx.x >> 11;
    __shared__ float qs[2][D_];
    __shared__ float sims[2][5 * SEL_BLK_];
    __shared__ float kT[5 * 64 * 33];     // per-warp [d][key] transposed K block
    __shared__ int   sblk[5];
    __shared__ int   sfl[5];
    __shared__ float red[2][2];
    int tid = threadIdx.x;                // 160 = 5 warps
    int w = tid >> 5, lane = tid & 31;
    if (tid < 5) {
        sblk[tid] = g_selidx[((size_t)kh * N_ + i) * 5 + tid];
        sfl[tid]  = (tid < 4) ? g_selflag[((size_t)kh * N_ + i) * 4 + tid] : 1;
    }
    if (tid < 128) {
        int g = tid >> 6, d = tid & 63;
        qs[g][d] = g_rq[(((size_t)(kh * GQ_ + g)) * N_ + i) * D_ + d];
    }
    __syncthreads();
    {
        // transpose-load this warp's K block (32 keys x 64 dims)
        int blk = sblk[w];
        const float* kbase = g_rk + ((size_t)kh * N_ + blk * SEL_BLK_) * D_;
        float* kw = kT + w * 64 * 33;
        for (int idx4 = lane; idx4 < 512; idx4 += 32) {
            int key = idx4 >> 4, d4 = (idx4 & 15) << 2;
            float4 v = *(const float4*)(kbase + key * D_ + d4);
            kw[(d4 + 0) * 33 + key] = v.x;
            kw[(d4 + 1) * 33 + key] = v.y;
            kw[(d4 + 2) * 33 + key] = v.z;
            kw[(d4 + 3) * 33 + key] = v.w;
        }
        __syncwarp();
        bool grpvalid = (w < 4) ? (sfl[w] != 0) : true;
        int lim = (w == 4) ? (i & 31) : 31;
        float s0 = -FLT_MAX / 10.f, s1 = -FLT_MAX / 10.f;
        if (grpvalid && lane <= lim) {
            float a0 = 0.f, a1 = 0.f;
#pragma unroll 8
            for (int d = 0; d < 64; d++) {
                float kv = kw[d * 33 + lane];
                a0 += qs[0][d] * kv;
                a1 += qs[1][d] * kv;
            }
            s0 = a0 * SCALE_; s1 = a1 * SCALE_;
        }
        sims[0][w * 32 + lane] = s0;
        sims[1][w * 32 + lane] = s1;
    }
    __syncthreads();
    if (tid < 64) {
        int g = tid >> 5, l = tid & 31;
        float m = -FLT_MAX;
        for (int j = l; j < 160; j += 32) m = fmaxf(m, sims[g][j]);
        for (int o = 16; o; o >>= 1) m = fmaxf(m, __shfl_xor_sync(0xffffffffu, m, o));
        float sm = 0.f;
        for (int j = l; j < 160; j += 32) sm += expf(sims[g][j] - m);
        for (int o = 16; o; o >>= 1) sm += __shfl_xor_sync(0xffffffffu, sm, o);
        if (l == 0) { red[g][0] = m; red[g][1] = sm; }
    }
    __syncthreads();
    for (int j = tid; j < 320; j += 160) {
        int g = j / 160, jj = j % 160;
        sims[g][jj] = expf(sims[g][jj] - red[g][0]) / red[g][1];
    }
    __syncthreads();
    if (tid < 128) {
        int g = tid >> 6, d = tid & 63;
        const float* vbase = g_qkv + (size_t)(H_ + KVH_) * D_ + kh * D_ + d;
        float acc = 0.f;
#pragma unroll
        for (int s = 0; s < 5; s++) {
            int pb = sblk[s] * SEL_BLK_;
#pragma unroll 8
            for (int t = 0; t < SEL_BLK_; t++)
                acc += sims[g][s * 32 + t] * vbase[(size_t)(pb + t) * QKVW_];
        }
        g_fout[(((size_t)(kh * GQ_ + g)) * N_ + i) * D_ + d] = acc;
    }
}

// ---------------- sliding-window attention ------------------------------------
__global__ void sattn_kernel() {
    extern __shared__ float sm[];
    float* Ks = sm;
    float* Qs = sm + 128 * 65;
    float* Ps = Qs + 64 * 65;
    int tIdx = blockIdx.x, h = blockIdx.y, kh = h >> 1;
    int i0 = tIdx * 64;
    int tid = threadIdx.x, w = tid >> 5, lane = tid & 31;
    for (int idx = tid; idx < 64 * 64; idx += 256) {
        int r = idx >> 6, d = idx & 63;
        Qs[r * 65 + d] = g_rq[((size_t)h * N_ + i0 + r) * D_ + d];
    }
    for (int idx = tid; idx < 128 * 64; idx += 256) {
        int j = idx >> 6, d = idx & 63;
        int p = i0 - 64 + j;
        Ks[j * 65 + d] = (p >= 0) ? g_rk[((size_t)kh * N_ + p) * D_ + d] : 0.f;
    }
    __syncthreads();
#pragma unroll
    for (int rr = 0; rr < 8; rr++) {
        int r = w * 8 + rr;
        int j0 = lane, j1 = lane + 32, j2 = lane + 64, j3 = lane + 96;
        float a0 = 0.f, a1 = 0.f, a2 = 0.f, a3 = 0.f;
        for (int d = 0; d < 64; d++) {
            float q = Qs[r * 65 + d];
            a0 += q * Ks[j0 * 65 + d]; a1 += q * Ks[j1 * 65 + d];
            a2 += q * Ks[j2 * 65 + d]; a3 += q * Ks[j3 * 65 + d];
        }
        float s0, s1, s2, s3;
        {
            bool ok;
            ok = (j0 >= r + 1) && (j0 <= r + 64) && (i0 - 64 + j0 >= 0);
            s0 = ok ? a0 * SCALE_ : -FLT_MAX;
            ok = (j1 >= r + 1) && (j1 <= r + 64) && (i0 - 64 + j1 >= 0);
            s1 = ok ? a1 * SCALE_ : -FLT_MAX;
            ok = (j2 >= r + 1) && (j2 <= r + 64) && (i0 - 64 + j2 >= 0);
            s2 = ok ? a2 * SCALE_ : -FLT_MAX;
            ok = (j3 >= r + 1) && (j3 <= r + 64) && (i0 - 64 + j3 >= 0);
            s3 = ok ? a3 * SCALE_ : -FLT_MAX;
        }
        float m = fmaxf(fmaxf(s0, s1), fmaxf(s2, s3));
        for (int o = 16; o; o >>= 1) m = fmaxf(m, __shfl_xor_sync(0xffffffffu, m, o));
        float e0 = expf(s0 - m), e1 = expf(s1 - m), e2 = expf(s2 - m), e3 = expf(s3 - m);
        float su = e0 + e1 + e2 + e3;
        for (int o = 16; o; o >>= 1) su += __shfl_xor_sync(0xffffffffu, su, o);
        float inv = 1.f / su;
        Ps[r * 128 + j0] = e0 * inv; Ps[r * 128 + j1] = e1 * inv;
        Ps[r * 128 + j2] = e2 * inv; Ps[r * 128 + j3] = e3 * inv;
    }
    __syncthreads();
    for (int idx = tid; idx < 128 * 64; idx += 256) {
        int j = idx >> 6, d = idx & 63;
        int p = i0 - 64 + j;
        Ks[j * 65 + d] = (p >= 0)
            ? g_qkv[(size_t)p * QKVW_ + (H_ + KVH_) * D_ + kh * D_ + d] : 0.f;
    }
    __syncthreads();
#pragma unroll
    for (int rr = 0; rr < 8; rr++) {
        int r = w * 8 + rr;
        float a0 = 0.f, a1 = 0.f;
        for (int j = 0; j < 128; j++) {
            float p = Ps[r * 128 + j];
            a0 += p * Ks[j * 65 + lane];
            a1 += p * Ks[j * 65 + lane + 32];
        }
        size_t ob = ((size_t)h * N_ + i0 + r) * D_;
        g_sout[ob + lane] = a0;
        g_sout[ob + lane + 32] = a1;
    }
}

// ---------------- gated combine ------------------------------------------------
__global__ void combine_kernel() {
    int idx = blockIdx.x * blockDim.x + threadIdx.x;
    if (idx >= N_ * H_ * D_) return;
    int d = idx % D_;
    int h = (idx / D_) % H_;
    int n = idx / (D_ * H_);
    const float* g = g_gates + ((size_t)n * H_ + h) * 3;
    size_t hnd = ((size_t)h * N_ + n) * D_ + d;
    g_comb[(size_t)n * DIM_ + h * D_ + d] =
        g[0] * g_cout[hnd] + g[1] * g_fout[hnd] + g[2] * g_sout[hnd];
}

// ---------------- launch -------------------------------------------------------
extern "C" void kernel_launch(void* const* d_in, const int* in_sizes, int n_in,
                              void* d_out, int out_size) {
    const float* inp    = (const float*)d_in[0];
    const float* norm_g = (const float*)d_in[1];
    const float* Wqkv   = (const float*)d_in[2];
    const float* mem_kv = (const float*)d_in[3];
    const float* k_pos  = (const float*)d_in[4];
    const float* v_pos  = (const float*)d_in[5];
    const float* kW1    = (const float*)d_in[6];
    const float* kb1    = (const float*)d_in[7];
    const float* kW2    = (const float*)d_in[8];
    const float* kb2    = (const float*)d_in[9];
    const float* vW1    = (const float*)d_in[10];
    const float* vb1    = (const float*)d_in[11];
    const float* vW2    = (const float*)d_in[12];
    const float* vb2    = (const float*)d_in[13];
    const float* combW  = (const float*)d_in[14];
    const float* combB  = (const float*)d_in[15];
    const float* Wout   = (const float*)d_in[16];
    float* out = (float*)d_out;

    float* px;     cudaGetSymbolAddress((void**)&px, g_x);
    float* pqkv;   cudaGetSymbolAddress((void**)&pqkv, g_qkv);
    float* pkw;    cudaGetSymbolAddress((void**)&pkw, g_kwflat);
    float* pvw;    cudaGetSymbolAddress((void**)&pvw, g_vwflat);
    float* ph1;    cudaGetSymbolAddress((void**)&ph1, g_h1);
    float* pckr;   cudaGetSymbolAddress((void**)&pckr, g_ckraw);
    float* pcvr;   cudaGetSymbolAddress((void**)&pcvr, g_cvraw);
    float* pckT;   cudaGetSymbolAddress((void**)&pckT, g_ckT);
    float* pcvp;   cudaGetSymbolAddress((void**)&pcvp, g_cvpad);
    float* pqc;    cudaGetSymbolAddress((void**)&pqc, g_qc);
    float* pcsim;  cudaGetSymbolAddress((void**)&pcsim, g_csim);
    float* pcout;  cudaGetSymbolAddress((void**)&pcout, g_cout);
    float* ppart;  cudaGetSymbolAddress((void**)&ppart, g_part);
    float* pgates; cudaGetSymbolAddress((void**)&pgates, g_gates);
    float* pcomb;  cudaGetSymbolAddress((void**)&pcomb, g_comb);
    __nv_bfloat16 *pah, *pal, *pbh, *pbl;
    cudaGetSymbolAddress((void**)&pah, g_ah);
    cudaGetSymbolAddress((void**)&pal, g_al);
    cudaGetSymbolAddress((void**)&pbh, g_bh);
    cudaGetSymbolAddress((void**)&pbl, g_bl);

    const int SATTN_SMEM = (128 * 65 + 64 * 65 + 64 * 128) * 4;
    cudaFuncSetAttribute(sattn_kernel, cudaFuncAttributeMaxDynamicSharedMemorySize, SATTN_SMEM);

    // 1. RMSNorm
    rmsnorm_kernel<<<N_, 256>>>(inp, norm_g);
    // 2. qkv = x @ Wqkv  (HMMA bf16 split)
    transpose_split_kernel<<<dim3(QKVW_ / 32, DIM_ / 32), dim3(32, 8)>>>(Wqkv, DIM_, QKVW_, pbh, pbl);
    split_kernel<<<(N_ * DIM_ + 255) / 256, 256>>>(px, N_ * DIM_, pah, pal);
    tcgemm_kernel<0, false><<<dim3(QKVW_ / 128, N_ / 128), 512>>>(
        pah, pal, pbh, pbl, nullptr, pqkv, QKVW_, N_, QKVW_, DIM_);
    // 3. windows + rope/qc
    build_windows_kernel<<<(KVH_ * NCB_ * CBS_ * D_ + 255) / 256, 256>>>(k_pos, v_pos);
    rope_kernel<<<((H_ + KVH_) * N_ * (D_ / 2) + 255) / 256, 256>>>();
    // 4a. k-compression MLP layer 1 (HMMA) + layer 2 (split-K x8)
    transpose_split_kernel<<<dim3(HID_ / 32, HID_ / 32), dim3(32, 8)>>>(kW1, HID_, HID_, pbh, pbl);
    split_kernel<<<(KVH_ * NCB_ * HID_ + 255) / 256, 256>>>(pkw, KVH_ * NCB_ * HID_, pah, pal);
    tcgemm_kernel<1, true><<<dim3(HID_ / 128, (KVH_ * NCB_) / 128), 512>>>(
        pah, pal, pbh, pbl, kb1, ph1, HID_, KVH_ * NCB_, HID_, HID_);
    sgemm_kernel<0, false><<<dim3(1, 16, 8), 256>>>(ph1, HID_, 256, kW2, D_, (long)256 * D_,
                                                    nullptr, ppart, D_, (long)1024 * D_,
                                                    KVH_ * NCB_, D_, 256);
    reduce8_kernel<0><<<(1024 * D_ + 255) / 256, 256>>>(ppart, kb2, pckr, 1024 * D_, D_);
    // 4b. v-compression MLP layer 1 (HMMA) + layer 2
    transpose_split_kernel<<<dim3(HID_ / 32, HID_ / 32), dim3(32, 8)>>>(vW1, HID_, HID_, pbh, pbl);
    split_kernel<<<(KVH_ * NCB_ * HID_ + 255) / 256, 256>>>(pvw, KVH_ * NCB_ * HID_, pah, pal);
    tcgemm_kernel<1, true><<<dim3(HID_ / 128, (KVH_ * NCB_) / 128), 512>>>(
        pah, pal, pbh, pbl, vb1, ph1, HID_, KVH_ * NCB_, HID_, HID_);
    sgemm_kernel<0, false><<<dim3(1, 16, 8), 256>>>(ph1, HID_, 256, vW2, D_, (long)256 * D_,
                                                    nullptr, ppart, D_, (long)1024 * D_,
                                                    KVH_ * NCB_, D_, 256);
    reduce8_kernel<0><<<(1024 * D_ + 255) / 256, 256>>>(ppart, vb2, pcvr, 1024 * D_, D_);
    // 5. assemble ckT / cvpad
    assemble_c_kernel<<<(KVH_ * CJP_ * D_ + 255) / 256, 256>>>(mem_kv);
    // 6. compressed attention (batched fp32 GEMMs + softmax)
    sgemm_kernel<0, false><<<dim3(3, 64, KVH_), 256>>>(
        pqc, D_, (long)(GQ_ * N_) * D_, pckT, CJP_, (long)D_ * CJP_, nullptr,
        pcsim, CJP_, (long)(GQ_ * N_) * CJP_, GQ_ * N_, CJ_, D_);
    importance_kernel<<<(KVH_ * N_ * NFB_ + 255) / 256, 256>>>();
    csoftmax_kernel<<<KVH_ * GQ_ * N_ / 8, 256>>>();
    sgemm_kernel<0, false><<<dim3(1, 64, KVH_), 256>>>(
        pcsim, CJP_, (long)(GQ_ * N_) * CJP_, pcvp, D_, (long)CJP_ * D_, nullptr,
        pcout, D_, (long)(GQ_ * N_) * D_, GQ_ * N_, D_, CJP_);
    // 7. top-k + fine attention
    topk_kernel<<<KVH_ * N_ / 8, 256>>>();
    fattn_kernel<<<KVH_ * N_, 160>>>();
    // 8. sliding-window attention
    sattn_kernel<<<dim3(N_ / 64, H_), 256, SATTN_SMEM>>>();
    // 9. gates (split-K x8) + combine
    sgemm_kernel<0, false><<<dim3(1, 32, 8), 256>>>(px, DIM_, 128, combW, 48, (long)128 * 48,
                                                    nullptr, ppart, 48, (long)N_ * 48,
                                                    N_, 48, 128);
    reduce8_kernel<2><<<(N_ * 48 + 255) / 256, 256>>>(ppart, combB, pgates, N_ * 48, 48);
    combine_kernel<<<(N_ * H_ * D_ + 255) / 256, 256>>>();
    // 10. out = comb @ Wout (HMMA)
    transpose_split_kernel<<<dim3(DIM_ / 32, DIM_ / 32), dim3(32, 8)>>>(Wout, DIM_, DIM_, pbh, pbl);
    split_kernel<<<(N_ * DIM_ + 255) / 256, 256>>>(pcomb, N_ * DIM_, pah, pal);
    tcgemm_kernel<0, false><<<dim3(DIM_ / 128, N_ / 128), 512>>>(
        pah, pal, pbh, pbl, nullptr, out, DIM_, N_, DIM_, DIM_);
}